// round 12
// baseline (speedup 1.0000x reference)
#include <cuda_runtime.h>
#include <cuda_fp16.h>
#include <math.h>
#include <stdint.h>

// ================= problem constants =================
namespace {
constexpr int Bb   = 256;
constexpr int Tt   = 15;
constexpr int Ns   = 8;
constexpr int Dd   = 64;
constexpr int U    = 2056;
constexpr int H    = 512;
constexpr int BUF  = 1680;
constexpr int XDIM = BUF + 2 * H;   // 2704
constexpr int GIN  = XDIM + U;      // 4760
constexpr int ROWS = Bb * Ns;       // 2048
constexpr int PROWS = ROWS * Ns;    // 16384
constexpr int DT   = Dd * Tt;       // 960
constexpr int NG   = 4 * U;         // 8224 fused (interleaved) gate width
constexpr int NG_SPLIT = 4096;      // pass-1 N split (u=1024 boundary, perm-clean)
constexpr int OUT_OFF_C   = ROWS * Dd;
constexpr int OUT_OFF_H   = OUT_OFF_C + ROWS * U;

// transposed-weight scratch offsets (halfs)
constexpr size_t OFF_BUF = 0;                                 // 1680 x 960
constexpr size_t OFF_R1A = OFF_BUF + (size_t)1680 * 960;      // 512 x 2056 (fused x3)
constexpr size_t OFF_R1B = OFF_R1A + (size_t)512 * 2056;
constexpr size_t OFF_L1A = OFF_R1B + (size_t)512 * 2056;
constexpr size_t OFF_L1B = OFF_L1A + (size_t)512 * 2056;      // 512 x 1680
constexpr size_t OFF_R2  = OFF_L1B + (size_t)512 * 1680;      // 512 x 512
constexpr size_t OFF_R3  = OFF_R2 + (size_t)512 * 512;
constexpr size_t OFF_L2  = OFF_R3 + (size_t)512 * 512;
constexpr size_t OFF_L3  = OFF_L2 + (size_t)512 * 512;
constexpr size_t OFF_G   = OFF_L3 + (size_t)512 * 512;        // 8224 x 4760 interleaved gates
constexpr size_t OFF_D   = OFF_G + (size_t)NG * 4760;         // 64 x 2056
constexpr size_t WT_TOTAL = OFF_D + (size_t)64 * 2056;
}

// ================= scratch (static device memory) =================
__device__ __half h_wt[WT_TOTAL];
__device__ __half h_zb[ROWS * DT];
__device__ __half h_cells[ROWS * U];
__device__ __half h_proj[ROWS * 1536];          // [ai | aj | al]
__device__ __half h_bl[ROWS * H];
__device__ __half h_rA[(size_t)PROWS * H];
__device__ __half h_rB[(size_t)PROWS * H];
__device__ __half h_rC[(size_t)PROWS * H];
__device__ __half h_rD[(size_t)PROWS * H];
__device__ __half h_xh[(size_t)ROWS * GIN];
__device__ __half h_hnew[ROWS * U];
__device__ float  g_part[(size_t)ROWS * NG];    // hidden-slice partial gate sums
__device__ float  g_bias[NG];

// ================= helpers =================
__device__ __forceinline__ uint32_t smem_u32(const void* p) {
    uint32_t a;
    asm("{ .reg .u64 t; cvta.to.shared.u64 t, %1; cvt.u32.u64 %0, t; }" : "=r"(a) : "l"(p));
    return a;
}

#define CP_ASYNC(dst, src, sz) \
    asm volatile("cp.async.cg.shared.global [%0], [%1], 16, %2;" \
        :: "r"(dst), "l"(src), "r"(sz))
#define CP_COMMIT() asm volatile("cp.async.commit_group;" ::: "memory")
#define CP_WAIT(N)  asm volatile("cp.async.wait_group %0;" :: "n"(N) : "memory")

#define MMA_F16(d, a, b) \
    asm volatile("mma.sync.aligned.m16n8k16.row.col.f32.f16.f16.f32 " \
        "{%0,%1,%2,%3}, {%4,%5,%6,%7}, {%8,%9}, {%0,%1,%2,%3};" \
        : "+f"((d)[0]), "+f"((d)[1]), "+f"((d)[2]), "+f"((d)[3]) \
        : "r"((a)[0]), "r"((a)[1]), "r"((a)[2]), "r"((a)[3]), \
          "r"((b)[0]), "r"((b)[1]))

#define LDMATRIX_X4(r0, r1, r2, r3, addr) \
    asm volatile("ldmatrix.sync.aligned.m8n8.x4.shared.b16 {%0,%1,%2,%3}, [%4];" \
        : "=r"(r0), "=r"(r1), "=r"(r2), "=r"(r3) : "r"(addr))

// ================= activations =================
// ACT: 0 none, 1 elu, 2 gelu, 3 sigmoid, 4 tanh, 5 fused-gate epilogue (w/ partial)
__device__ __forceinline__ float act_apply(float x, int ACT) {
    if (ACT == 1) return x > 0.f ? x : expm1f(x);
    if (ACT == 2) return 0.5f * x * (1.f + erff(x * 0.70710678118654752440f));
    if (ACT == 3) return 1.f / (1.f + expf(-x));
    if (ACT == 4) return tanhf(x);
    return x;
}
__device__ __forceinline__ float sigmoidf_(float x) { return 1.f / (1.f + expf(-x)); }

// ================= fp16 mma GEMM (3-stage cp.async + ldmatrix) =================
// C = act(A @ Wt^T + bias). A: (M,K) halfs stride lda. Wt: (Nd,K) halfs stride ldw.
// CTA tile 128 x (32*NI) x 64. 256 thr, 8 warps (2m x 4n), warp tile 64 x (8*NI).
// ACT==5 (NI==8): interleaved-gate LSTM epilogue, adds `partial` before activation.
template <int ACT, bool HOUT, int NI>
__global__ void __launch_bounds__(256, 1)
hgemm(const __half* __restrict__ A, int lda,
      const __half* __restrict__ Wt, int ldw,
      const float* __restrict__ bias,
      void* __restrict__ Cv, int ldc,
      int M, int Nd, int K,
      const float* __restrict__ partial,
      const float* __restrict__ cells,
      float* __restrict__ outC,
      float* __restrict__ outH,
      __half* __restrict__ outHh) {
    constexpr int BN = 32 * NI;
    constexpr int STG = (128 + BN) * 64 * 2;     // bytes per stage
    extern __shared__ __align__(16) char smraw[];

    const int tid = threadIdx.x;
    const int lane = tid & 31;
    const int wid = tid >> 5;
    const int g = lane >> 2, t = lane & 3;
    const int wm = wid >> 2, wn = wid & 3;
    const int bm = blockIdx.y * 128, bn = blockIdx.x * BN;

    float acc[4][NI][4];
#pragma unroll
    for (int i = 0; i < 4; i++)
#pragma unroll
        for (int j = 0; j < NI; j++)
#pragma unroll
            for (int q = 0; q < 4; q++) acc[i][j][q] = 0.f;

    const int nt = (K + 63) / 64;

    auto load_tile = [&](int kt, int s) {
        __half* As = (__half*)(smraw + s * STG);
        __half* Bs = As + 8192;
        const int k0 = kt * 64;
#pragma unroll
        for (int i = 0; i < 4; i++) {
            int idx = tid + i * 256;
            int row = idx >> 3, c8 = idx & 7;
            int kk = k0 + c8 * 8;
            uint32_t dst = smem_u32(As + row * 64 + ((c8 ^ (row & 7)) << 3));
            const __half* src = A + (size_t)(bm + row) * lda + kk;
            int sz = (kk < K) ? 16 : 0;
            CP_ASYNC(dst, src, sz);
        }
#pragma unroll
        for (int i = 0; i < NI; i++) {
            int idx = tid + i * 256;
            int row = idx >> 3, c8 = idx & 7;
            int kk = k0 + c8 * 8;
            int n = bn + row;
            int nc = (n < Nd) ? n : (Nd - 1);
            uint32_t dst = smem_u32(Bs + row * 64 + ((c8 ^ (row & 7)) << 3));
            const __half* src = Wt + (size_t)nc * ldw + kk;
            int sz = (n < Nd && kk < K) ? 16 : 0;
            CP_ASYNC(dst, src, sz);
        }
    };

    // ldmatrix lane decomposition
    const int lm = lane >> 3, lr = lane & 7;

    auto compute_tile = [&](int s) {
        const uint32_t sbase = smem_u32(smraw + s * STG);
        const uint32_t a_base = sbase + (uint32_t)(wm * 64 + (lm & 1) * 8 + lr) * 128;
        const int ad = lm >> 1;
        const uint32_t b_base = sbase + 16384u + (uint32_t)(wn * (8 * NI) + (lm >> 1) * 8 + lr) * 128;
        const int bd = lm & 1;
#pragma unroll
        for (int ks = 0; ks < 4; ks++) {
            uint32_t a[4][4], b[NI][2];
#pragma unroll
            for (int mi = 0; mi < 4; mi++) {
                uint32_t addr = a_base + (uint32_t)(mi * 16 * 128) + ((uint32_t)((2 * ks + ad) ^ lr) << 4);
                LDMATRIX_X4(a[mi][0], a[mi][1], a[mi][2], a[mi][3], addr);
            }
#pragma unroll
            for (int np = 0; np < NI / 2; np++) {
                uint32_t addr = b_base + (uint32_t)(np * 16 * 128) + ((uint32_t)((2 * ks + bd) ^ lr) << 4);
                LDMATRIX_X4(b[2 * np][0], b[2 * np][1], b[2 * np + 1][0], b[2 * np + 1][1], addr);
            }
#pragma unroll
            for (int mi = 0; mi < 4; mi++)
#pragma unroll
                for (int ni = 0; ni < NI; ni++)
                    MMA_F16(acc[mi][ni], a[mi], b[ni]);
        }
    };

    // 3-stage pipeline, one __syncthreads per K-tile
    load_tile(0, 0);
    CP_COMMIT();
    load_tile(1, 1);
    CP_COMMIT();
    int s = 0;
    for (int kt = 0; kt < nt; kt++) {
        if (kt + 1 < nt) { CP_WAIT(1); } else { CP_WAIT(0); }
        __syncthreads();
        compute_tile(s);
        if (kt + 2 < nt) {
            int s2 = s + 2; if (s2 >= 3) s2 -= 3;
            load_tile(kt + 2, s2);
            CP_COMMIT();
        }
        if (++s == 3) s = 0;
    }

    if (ACT == 5) {
        // fused LSTM-gate epilogue (NI == 8, interleaved layout) + partial add
#pragma unroll
        for (int blk = 0; blk < 2; blk++) {
            const int base = bn + wn * 64 + blk * 32;
            if (base >= Nd) continue;
            const int ub = base >> 5;
            const int u = ub * 8 + 2 * t;
            const int colI = base + 2 * t;
            const float bI0 = bias[colI],      bI1 = bias[colI + 1];
            const float bF0 = bias[colI + 8],  bF1 = bias[colI + 9];
            const float bO0 = bias[colI + 16], bO1 = bias[colI + 17];
            const float bC0 = bias[colI + 24], bC1 = bias[colI + 25];
#pragma unroll
            for (int mi = 0; mi < 4; mi++) {
                const int r0 = bm + wm * 64 + mi * 16 + g;
#pragma unroll
                for (int half_ = 0; half_ < 2; half_++) {
                    const int r = r0 + half_ * 8;
                    const int e0 = half_ * 2, e1 = half_ * 2 + 1;
                    const float* prow = partial + (size_t)r * NG + colI;
                    float2 pI = *(const float2*)(prow);
                    float2 pF = *(const float2*)(prow + 8);
                    float2 pO = *(const float2*)(prow + 16);
                    float2 pC = *(const float2*)(prow + 24);
                    float I0 = sigmoidf_(acc[mi][blk * 4 + 0][e0] + pI.x + bI0);
                    float I1 = sigmoidf_(acc[mi][blk * 4 + 0][e1] + pI.y + bI1);
                    float F0 = sigmoidf_(acc[mi][blk * 4 + 1][e0] + pF.x + bF0);
                    float F1 = sigmoidf_(acc[mi][blk * 4 + 1][e1] + pF.y + bF1);
                    float O0 = sigmoidf_(acc[mi][blk * 4 + 2][e0] + pO.x + bO0);
                    float O1 = sigmoidf_(acc[mi][blk * 4 + 2][e1] + pO.y + bO1);
                    float T0 = tanhf(acc[mi][blk * 4 + 3][e0] + pC.x + bC0);
                    float T1 = tanhf(acc[mi][blk * 4 + 3][e1] + pC.y + bC1);
                    float2 cv = *(const float2*)(cells + (size_t)r * U + u);
                    float c0 = F0 * cv.x + I0 * T0;
                    float c1 = F1 * cv.y + I1 * T1;
                    float hh0 = O0 * tanhf(c0);
                    float hh1 = O1 * tanhf(c1);
                    *(float2*)(outC + (size_t)r * U + u) = make_float2(c0, c1);
                    *(float2*)(outH + (size_t)r * U + u) = make_float2(hh0, hh1);
                    *(__half2*)(outHh + (size_t)r * U + u) = __floats2half2_rn(hh0, hh1);
                }
            }
        }
        return;
    }

#pragma unroll
    for (int ni = 0; ni < NI; ni++) {
        const int col0 = bn + wn * (8 * NI) + ni * 8 + 2 * t;
        if (col0 >= Nd) continue;
        const float b0 = bias ? bias[col0] : 0.f;
        const float b1 = bias ? bias[col0 + 1] : 0.f;
#pragma unroll
        for (int mi = 0; mi < 4; mi++) {
            const int r0 = bm + wm * 64 + mi * 16 + g;
            float v0 = act_apply(acc[mi][ni][0] + b0, ACT);
            float v1 = act_apply(acc[mi][ni][1] + b1, ACT);
            float v2 = act_apply(acc[mi][ni][2] + b0, ACT);
            float v3 = act_apply(acc[mi][ni][3] + b1, ACT);
            if (HOUT) {
                __half* C = (__half*)Cv;
                *(__half2*)(C + (size_t)r0 * ldc + col0)       = __floats2half2_rn(v0, v1);
                *(__half2*)(C + (size_t)(r0 + 8) * ldc + col0) = __floats2half2_rn(v2, v3);
            } else {
                float* C = (float*)Cv;
                *(float2*)(C + (size_t)r0 * ldc + col0)       = make_float2(v0, v1);
                *(float2*)(C + (size_t)(r0 + 8) * ldc + col0) = make_float2(v2, v3);
            }
        }
    }
}

// ================= fast weight transpose + fp16 =================
// W (K,N) f32 (source row stride = N) -> Wt (N,K-range) f16 with dst row stride ldt.
// PERM: output row = (n>>3)*32 + gate*8 + (n&7)
template <bool PERM>
__global__ void wtrans_k(const float* __restrict__ W, __half* __restrict__ Wt,
                         int K, int N, int gate, int ldt) {
    __shared__ float ts[64][65];
    const int kb = blockIdx.y * 64, nb = blockIdx.x * 64;
    const int tid = threadIdx.x;
#pragma unroll
    for (int i = 0; i < 4; i++) {
        int idx = tid + i * 256;
        int k = idx >> 4, q = idx & 15;
        int gk = kb + k, gn = nb + q * 4;
        float4 v = make_float4(0.f, 0.f, 0.f, 0.f);
        if (gk < K && gn < N) v = *(const float4*)(W + (size_t)gk * N + gn);
        ts[k][q * 4 + 0] = v.x;
        ts[k][q * 4 + 1] = v.y;
        ts[k][q * 4 + 2] = v.z;
        ts[k][q * 4 + 3] = v.w;
    }
    __syncthreads();
#pragma unroll
    for (int i = 0; i < 2; i++) {
        int idx = tid + i * 256;
        int n = idx >> 3, c = idx & 7;
        int gn = nb + n;
        int gk = kb + c * 8;
        if (gn >= N || gk >= K) continue;
        __half hv[8];
#pragma unroll
        for (int j = 0; j < 8; j++) hv[j] = __float2half_rn(ts[c * 8 + j][n]);
        int row = PERM ? (((gn >> 3) << 5) + gate * 8 + (gn & 7)) : gn;
        *(uint4*)(Wt + (size_t)row * ldt + gk) = *(uint4*)hv;
    }
}

// ================= pointwise kernels =================
__global__ void transpose_z_k(const float* __restrict__ z, __half* __restrict__ zb) {
    int idx = blockIdx.x * blockDim.x + threadIdx.x;
    if (idx >= ROWS * DT) return;
    int bn = idx / DT;
    int rem = idx - bn * DT;
    int d = rem / Tt;
    int t = rem - d * Tt;
    int b = bn >> 3;
    int n = bn & 7;
    zb[idx] = __float2half_rn(z[((size_t)(b * Tt + t) * Ns + n) * Dd + d]);
}

__global__ void round_copy_k(const float* __restrict__ src, __half* __restrict__ dst, int n) {
    int idx = blockIdx.x * blockDim.x + threadIdx.x;
    if (idx >= n) return;
    dst[idx] = __float2half_rn(src[idx]);
}

__global__ void fuse_bias_perm_k(const float* __restrict__ bI, const float* __restrict__ bF,
                                 const float* __restrict__ bO, const float* __restrict__ bC,
                                 float* __restrict__ dst) {
    int idx = blockIdx.x * blockDim.x + threadIdx.x;
    if (idx >= NG) return;
    int gate = idx / U, u = idx - gate * U;
    const float* src = (gate == 0) ? bI : (gate == 1) ? bF : (gate == 2) ? bO : bC;
    dst[((u >> 3) << 5) + gate * 8 + (u & 7)] = src[u];
}

__global__ void pair_combine_k(const __half* __restrict__ ai, int ldi,
                               const __half* __restrict__ aj, int ldj,
                               const float* __restrict__ bias, __half* __restrict__ out) {
    int idx = blockIdx.x * blockDim.x + threadIdx.x;   // over PROWS * (H/2)
    if (idx >= PROWS * (H / 2)) return;
    int row = idx / (H / 2);
    int h2 = idx - row * (H / 2);
    int j = row & 7;
    int i_row = row >> 3;
    int b = i_row >> 3;
    int j_row = (b << 3) + j;

    float2 a = __half22float2(*((const __half2*)(ai + (size_t)i_row * ldi) + h2));
    float2 c = __half22float2(*((const __half2*)(aj + (size_t)j_row * ldj) + h2));
    float2 bb = ((const float2*)bias)[h2];
    float o0 = act_apply(a.x + c.x + bb.x, 2);
    float o1 = act_apply(a.y + c.y + bb.y, 2);
    ((__half2*)(out + (size_t)row * H))[h2] = __floats2half2_rn(o0, o1);
}

__global__ void reduce_inter_k(const __half* __restrict__ rA, const __half* __restrict__ rB,
                               __half* __restrict__ xh) {
    int idx = blockIdx.x * blockDim.x + threadIdx.x;   // over ROWS * (H/2)
    if (idx >= ROWS * (H / 2)) return;
    int row = idx / (H / 2);
    int h2 = idx - row * (H / 2);
    float s0 = 0.f, s1 = 0.f, m0 = -INFINITY, m1 = -INFINITY;
#pragma unroll
    for (int j = 0; j < Ns; j++) {
        size_t p = (size_t)(row * Ns + j) * (H / 2) + h2;
        float2 va = __half22float2(((const __half2*)rA)[p]);
        float2 vb = __half22float2(((const __half2*)rB)[p]);
        float v0 = va.x + vb.x, v1 = va.y + vb.y;
        s0 += v0; s1 += v1;
        m0 = fmaxf(m0, v0); m1 = fmaxf(m1, v1);
    }
    __half* base = xh + (size_t)row * GIN;
    *(__half2*)(base + BUF + 2 * h2)     = __floats2half2_rn(s0, s1);
    *(__half2*)(base + BUF + H + 2 * h2) = __floats2half2_rn(m0, m1);
}

__global__ void copy_hidden_k(const float* __restrict__ hidden, __half* __restrict__ xh) {
    int idx = blockIdx.x * blockDim.x + threadIdx.x;   // over ROWS * (U/2)
    if (idx >= ROWS * (U / 2)) return;
    int row = idx / (U / 2);
    int c2 = idx - row * (U / 2);
    float2 v = ((const float2*)(hidden + (size_t)row * U))[c2];
    *(__half2*)(xh + (size_t)row * GIN + XDIM + 2 * c2) = __floats2half2_rn(v.x, v.y);
}

// ================= host =================
template <int ACT, bool HOUT, int NI>
static void launch_hg(cudaStream_t st,
                      const __half* A, int lda, const __half* Wt, int ldw,
                      const float* bias,
                      void* C, int ldc, int M, int Nd, int K,
                      const float* partial = nullptr,
                      const float* cells = nullptr, float* outC = nullptr,
                      float* outH = nullptr, __half* outHh = nullptr) {
    constexpr int BN = 32 * NI;
    constexpr int smem = 3 * ((128 + BN) * 64 * 2);
    cudaFuncSetAttribute(hgemm<ACT, HOUT, NI>, cudaFuncAttributeMaxDynamicSharedMemorySize, smem);
    dim3 grid((Nd + BN - 1) / BN, M / 128);
    hgemm<ACT, HOUT, NI><<<grid, 256, smem, st>>>(A, lda, Wt, ldw, bias, C, ldc, M, Nd, K,
                                                  partial, cells, outC, outH, outHh);
}

template <bool PERM>
static void launch_wtrans(cudaStream_t st, const float* W, __half* Wt, int K, int N,
                          int gate = 0, int ldt = -1) {
    if (ldt < 0) ldt = K;
    dim3 grid((N + 63) / 64, (K + 63) / 64);
    wtrans_k<PERM><<<grid, 256, 0, st>>>(W, Wt, K, N, gate, ldt);
}

// Persistent stream/event pool (created once on the pre-baseline correctness
// run; reused by every captured call; never destroyed).
namespace {
struct StreamPool {
    cudaStream_t s1, s2, s3;
    cudaEvent_t evFork, evHid, evS1, evS3, evProj, evBl, evS2;
    StreamPool() {
        cudaStreamCreateWithFlags(&s1, cudaStreamNonBlocking);
        cudaStreamCreateWithFlags(&s2, cudaStreamNonBlocking);
        cudaStreamCreateWithFlags(&s3, cudaStreamNonBlocking);
        cudaEventCreateWithFlags(&evFork, cudaEventDisableTiming);
        cudaEventCreateWithFlags(&evHid,  cudaEventDisableTiming);
        cudaEventCreateWithFlags(&evS1,   cudaEventDisableTiming);
        cudaEventCreateWithFlags(&evS3,   cudaEventDisableTiming);
        cudaEventCreateWithFlags(&evProj, cudaEventDisableTiming);
        cudaEventCreateWithFlags(&evBl,   cudaEventDisableTiming);
        cudaEventCreateWithFlags(&evS2,   cudaEventDisableTiming);
    }
};
}

extern "C" void kernel_launch(void* const* d_in, const int* in_sizes, int n_in,
                              void* d_out, int out_size) {
    const float* z      = (const float*)d_in[0];
    const float* Cells  = (const float*)d_in[1];
    const float* hidden = (const float*)d_in[2];
    const float* W_buf  = (const float*)d_in[3];
    const float* b_buf  = (const float*)d_in[4];
    const float* W_r1   = (const float*)d_in[5];
    const float* b_r1   = (const float*)d_in[6];
    const float* W_r2   = (const float*)d_in[7];
    const float* b_r2   = (const float*)d_in[8];
    const float* W_r3   = (const float*)d_in[9];
    const float* b_r3   = (const float*)d_in[10];
    const float* W_l1   = (const float*)d_in[11];
    const float* b_l1   = (const float*)d_in[12];
    const float* W_l2   = (const float*)d_in[13];
    const float* b_l2   = (const float*)d_in[14];
    const float* W_l3   = (const float*)d_in[15];
    const float* b_l3   = (const float*)d_in[16];
    const float* W_I    = (const float*)d_in[17];
    const float* b_I    = (const float*)d_in[18];
    const float* W_F    = (const float*)d_in[19];
    const float* b_F    = (const float*)d_in[20];
    const float* W_O    = (const float*)d_in[21];
    const float* b_O    = (const float*)d_in[22];
    const float* W_C    = (const float*)d_in[23];
    const float* b_C    = (const float*)d_in[24];
    const float* W_d    = (const float*)d_in[25];
    const float* b_d    = (const float*)d_in[26];

    float* out = (float*)d_out;

    __half *wt, *zb, *cellsH, *proj, *bl, *rA, *rB, *rC, *rD, *xh, *hnewH;
    float *biasG, *gpart;
    cudaGetSymbolAddress((void**)&wt, h_wt);
    cudaGetSymbolAddress((void**)&zb, h_zb);
    cudaGetSymbolAddress((void**)&cellsH, h_cells);
    cudaGetSymbolAddress((void**)&proj, h_proj);
    cudaGetSymbolAddress((void**)&bl, h_bl);
    cudaGetSymbolAddress((void**)&rA, h_rA);
    cudaGetSymbolAddress((void**)&rB, h_rB);
    cudaGetSymbolAddress((void**)&rC, h_rC);
    cudaGetSymbolAddress((void**)&rD, h_rD);
    cudaGetSymbolAddress((void**)&xh, h_xh);
    cudaGetSymbolAddress((void**)&hnewH, h_hnew);
    cudaGetSymbolAddress((void**)&biasG, g_bias);
    cudaGetSymbolAddress((void**)&gpart, g_part);

    static StreamPool pool;
    cudaStream_t s1 = pool.s1, s2 = pool.s2, s3 = pool.s3;
    cudaStream_t m = 0;       // capturing (legacy) stream

    cudaEventRecord(pool.evFork, m);

    // ---- s1: HIDDEN K-rows of gate weights first, then copy_hidden (pass-1 deps)
    cudaStreamWaitEvent(s1, pool.evFork, 0);
    launch_wtrans<true>(s1, W_I + (size_t)XDIM * U, wt + OFF_G + XDIM, U, U, 0, GIN);
    launch_wtrans<true>(s1, W_F + (size_t)XDIM * U, wt + OFF_G + XDIM, U, U, 1, GIN);
    launch_wtrans<true>(s1, W_O + (size_t)XDIM * U, wt + OFF_G + XDIM, U, U, 2, GIN);
    launch_wtrans<true>(s1, W_C + (size_t)XDIM * U, wt + OFF_G + XDIM, U, U, 3, GIN);
    fuse_bias_perm_k<<<(NG + 255) / 256, 256, 0, s1>>>(b_I, b_F, b_O, b_C, biasG);
    copy_hidden_k<<<(ROWS * (U / 2) + 255) / 256, 256, 0, s1>>>(hidden, xh);
    cudaEventRecord(pool.evHid, s1);

    // ---- s1: pass-1 half A (N = [0, NG_SPLIT)), then low-K gate wtrans
    launch_hg<0, false, 8>(s1, xh + XDIM, GIN, wt + OFF_G + XDIM, GIN, nullptr,
                           gpart, NG, ROWS, NG_SPLIT, U);
    launch_wtrans<true>(s1, W_I, wt + OFF_G, XDIM, U, 0, GIN);
    launch_wtrans<true>(s1, W_F, wt + OFF_G, XDIM, U, 1, GIN);
    launch_wtrans<true>(s1, W_O, wt + OFF_G, XDIM, U, 2, GIN);
    launch_wtrans<true>(s1, W_C, wt + OFF_G, XDIM, U, 3, GIN);
    cudaEventRecord(pool.evS1, s1);

    // ---- s3: pass-1 half B (N = [NG_SPLIT, NG))
    cudaStreamWaitEvent(s3, pool.evHid, 0);
    launch_hg<0, false, 8>(s3, xh + XDIM, GIN,
                           wt + OFF_G + XDIM + (size_t)NG_SPLIT * GIN, GIN, nullptr,
                           gpart + NG_SPLIT, NG, ROWS, NG - NG_SPLIT, U);
    cudaEventRecord(pool.evS3, s3);

    // ---- s2: projection path (concurrent with main's buffer GEMM)
    cudaStreamWaitEvent(s2, pool.evFork, 0);
    launch_wtrans<false>(s2, W_r1,                 wt + OFF_R1A, U, H);
    launch_wtrans<false>(s2, W_r1 + (size_t)U * H, wt + OFF_R1B, U, H);
    launch_wtrans<false>(s2, W_l1,                 wt + OFF_L1A, U, H);
    round_copy_k<<<(ROWS * U + 255) / 256, 256, 0, s2>>>(Cells, cellsH, ROWS * U);
    launch_hg<0, true, 4>(s2, cellsH, U, wt + OFF_R1A, U, nullptr, proj, 1536, ROWS, 1536, U);
    cudaEventRecord(pool.evProj, s2);
    launch_wtrans<false>(s2, W_l2, wt + OFF_L2, H, H);
    launch_wtrans<false>(s2, W_l3, wt + OFF_L3, H, H);

    // ---- main: buffer path
    launch_wtrans<false>(m, W_buf, wt + OFF_BUF, DT, BUF);
    launch_wtrans<false>(m, W_l1 + (size_t)U * H, wt + OFF_L1B, BUF, H);
    launch_wtrans<false>(m, W_r2, wt + OFF_R2, H, H);
    launch_wtrans<false>(m, W_r3, wt + OFF_R3, H, H);
    launch_wtrans<false>(m, W_d, wt + OFF_D, U, Dd);
    transpose_z_k<<<(ROWS * DT + 255) / 256, 256, 0, m>>>(z, zb);
    launch_hg<1, true, 4>(m, zb, DT, wt + OFF_BUF, DT, b_buf, xh, GIN, ROWS, BUF, DT);
    launch_hg<0, true, 4>(m, xh, GIN, wt + OFF_L1B, BUF, nullptr, bl, H, ROWS, H, BUF);
    cudaEventRecord(pool.evBl, m);

    // ---- s2: lambda path (combine -> rC, l2 -> rD, l3 -> rC)
    cudaStreamWaitEvent(s2, pool.evBl, 0);
    pair_combine_k<<<(PROWS * (H / 2) + 255) / 256, 256, 0, s2>>>(proj + 1024, 1536, bl, H, b_l1, rC);
    launch_hg<2, true, 8>(s2, rC, H, wt + OFF_L2, H, b_l2, rD, H, PROWS, H, H);
    launch_hg<2, true, 8>(s2, rD, H, wt + OFF_L3, H, b_l3, rC, H, PROWS, H, H);
    cudaEventRecord(pool.evS2, s2);

    // ---- main: rho path (combine -> rA, r2 -> rB, r3 -> rA)
    cudaStreamWaitEvent(m, pool.evProj, 0);
    pair_combine_k<<<(PROWS * (H / 2) + 255) / 256, 256, 0, m>>>(proj, 1536, proj + 512, 1536, b_r1, rA);
    launch_hg<2, true, 8>(m, rA, H, wt + OFF_R2, H, b_r2, rB, H, PROWS, H, H);
    launch_hg<2, true, 8>(m, rB, H, wt + OFF_R3, H, b_r3, rA, H, PROWS, H, H);

    // ---- join: reduce, then final gate pass (K = XDIM) with fused LSTM epilogue
    cudaStreamWaitEvent(m, pool.evS2, 0);
    reduce_inter_k<<<(ROWS * (H / 2) + 255) / 256, 256, 0, m>>>(rA, rC, xh);
    cudaStreamWaitEvent(m, pool.evS1, 0);
    cudaStreamWaitEvent(m, pool.evS3, 0);
    launch_hg<5, false, 8>(m, xh, GIN, wt + OFF_G, GIN, biasG,
                           nullptr, 0, ROWS, NG, XDIM,
                           gpart, Cells, out + OUT_OFF_C, out + OUT_OFF_H, hnewH);

    // ---- decode
    launch_hg<0, false, 4>(m, hnewH, U, wt + OFF_D, U, b_d, out, Dd, ROWS, Dd, U);
}

// round 13
// speedup vs baseline: 1.4804x; 1.4804x over previous
#include <cuda_runtime.h>
#include <cuda_fp16.h>
#include <math.h>
#include <stdint.h>

// ================= problem constants =================
namespace {
constexpr int Bb   = 256;
constexpr int Tt   = 15;
constexpr int Ns   = 8;
constexpr int Dd   = 64;
constexpr int U    = 2056;
constexpr int H    = 512;
constexpr int BUF  = 1680;
constexpr int XDIM = BUF + 2 * H;   // 2704
constexpr int GIN  = XDIM + U;      // 4760
constexpr int ROWS = Bb * Ns;       // 2048
constexpr int PROWS = ROWS * Ns;    // 16384
constexpr int DT   = Dd * Tt;       // 960
constexpr int NG   = 4 * U;         // 8224 fused (interleaved) gate width
constexpr int OUT_OFF_C   = ROWS * Dd;
constexpr int OUT_OFF_H   = OUT_OFF_C + ROWS * U;

// transposed-weight scratch offsets (halfs)
constexpr size_t OFF_BUF = 0;                                 // 1680 x 960
constexpr size_t OFF_R1A = OFF_BUF + (size_t)1680 * 960;      // 512 x 2056 (fused x3)
constexpr size_t OFF_R1B = OFF_R1A + (size_t)512 * 2056;
constexpr size_t OFF_L1A = OFF_R1B + (size_t)512 * 2056;
constexpr size_t OFF_L1B = OFF_L1A + (size_t)512 * 2056;      // 512 x 1680
constexpr size_t OFF_R2  = OFF_L1B + (size_t)512 * 1680;      // 512 x 512
constexpr size_t OFF_R3  = OFF_R2 + (size_t)512 * 512;
constexpr size_t OFF_L2  = OFF_R3 + (size_t)512 * 512;
constexpr size_t OFF_L3  = OFF_L2 + (size_t)512 * 512;
constexpr size_t OFF_G   = OFF_L3 + (size_t)512 * 512;        // 8224 x 4760 interleaved gates
constexpr size_t OFF_D   = OFF_G + (size_t)NG * 4760;         // 64 x 2056
constexpr size_t WT_TOTAL = OFF_D + (size_t)64 * 2056;
}

// ================= scratch (static device memory) =================
__device__ __half h_wt[WT_TOTAL];
__device__ __half h_zb[ROWS * DT];
__device__ __half h_cells[ROWS * U];
__device__ __half h_proj[ROWS * 1536];          // [ai | aj | al]
__device__ __half h_bl[ROWS * H];
__device__ __half h_rA[(size_t)PROWS * H];
__device__ __half h_rB[(size_t)PROWS * H];
__device__ __half h_rC[(size_t)PROWS * H];
__device__ __half h_rD[(size_t)PROWS * H];
__device__ __half h_xh[(size_t)ROWS * GIN];
__device__ __half h_hnew[ROWS * U];
__device__ float  g_part[(size_t)ROWS * NG];    // hidden-slice partial gate sums
__device__ float  g_bias[NG];

// ================= helpers =================
__device__ __forceinline__ uint32_t smem_u32(const void* p) {
    uint32_t a;
    asm("{ .reg .u64 t; cvta.to.shared.u64 t, %1; cvt.u32.u64 %0, t; }" : "=r"(a) : "l"(p));
    return a;
}

#define CP_ASYNC(dst, src, sz) \
    asm volatile("cp.async.cg.shared.global [%0], [%1], 16, %2;" \
        :: "r"(dst), "l"(src), "r"(sz))
#define CP_COMMIT() asm volatile("cp.async.commit_group;" ::: "memory")
#define CP_WAIT(N)  asm volatile("cp.async.wait_group %0;" :: "n"(N) : "memory")

#define MMA_F16(d, a, b) \
    asm volatile("mma.sync.aligned.m16n8k16.row.col.f32.f16.f16.f32 " \
        "{%0,%1,%2,%3}, {%4,%5,%6,%7}, {%8,%9}, {%0,%1,%2,%3};" \
        : "+f"((d)[0]), "+f"((d)[1]), "+f"((d)[2]), "+f"((d)[3]) \
        : "r"((a)[0]), "r"((a)[1]), "r"((a)[2]), "r"((a)[3]), \
          "r"((b)[0]), "r"((b)[1]))

#define LDMATRIX_X4(r0, r1, r2, r3, addr) \
    asm volatile("ldmatrix.sync.aligned.m8n8.x4.shared.b16 {%0,%1,%2,%3}, [%4];" \
        : "=r"(r0), "=r"(r1), "=r"(r2), "=r"(r3) : "r"(addr))

// ================= activations =================
// ACT: 0 none, 1 elu, 2 gelu, 3 sigmoid, 4 tanh, 5 fused-gate epilogue (w/ partial)
__device__ __forceinline__ float act_apply(float x, int ACT) {
    if (ACT == 1) return x > 0.f ? x : expm1f(x);
    if (ACT == 2) return 0.5f * x * (1.f + erff(x * 0.70710678118654752440f));
    if (ACT == 3) return 1.f / (1.f + expf(-x));
    if (ACT == 4) return tanhf(x);
    return x;
}
__device__ __forceinline__ float sigmoidf_(float x) { return 1.f / (1.f + expf(-x)); }

// ================= fp16 mma GEMM (4-stage cp.async + ldmatrix) =================
// C = act(A @ Wt^T + bias). A: (M,K) halfs stride lda. Wt: (Nd,K) halfs stride ldw.
// CTA tile 128 x (32*NI) x 64. 256 thr, 8 warps (2m x 4n), warp tile 64 x (8*NI).
// ACT==5 (NI==8): interleaved-gate LSTM epilogue, adds `partial` before activation.
template <int ACT, bool HOUT, int NI>
__global__ void __launch_bounds__(256, 1)
hgemm(const __half* __restrict__ A, int lda,
      const __half* __restrict__ Wt, int ldw,
      const float* __restrict__ bias,
      void* __restrict__ Cv, int ldc,
      int M, int Nd, int K,
      const float* __restrict__ partial,
      const float* __restrict__ cells,
      float* __restrict__ outC,
      float* __restrict__ outH,
      __half* __restrict__ outHh) {
    constexpr int BN = 32 * NI;
    constexpr int STG = (128 + BN) * 64 * 2;     // bytes per stage
    extern __shared__ __align__(16) char smraw[];

    const int tid = threadIdx.x;
    const int lane = tid & 31;
    const int wid = tid >> 5;
    const int g = lane >> 2, t = lane & 3;
    const int wm = wid >> 2, wn = wid & 3;
    const int bm = blockIdx.y * 128, bn = blockIdx.x * BN;

    float acc[4][NI][4];
#pragma unroll
    for (int i = 0; i < 4; i++)
#pragma unroll
        for (int j = 0; j < NI; j++)
#pragma unroll
            for (int q = 0; q < 4; q++) acc[i][j][q] = 0.f;

    const int nt = (K + 63) / 64;

    auto load_tile = [&](int kt, int s) {
        __half* As = (__half*)(smraw + s * STG);
        __half* Bs = As + 8192;
        const int k0 = kt * 64;
#pragma unroll
        for (int i = 0; i < 4; i++) {
            int idx = tid + i * 256;
            int row = idx >> 3, c8 = idx & 7;
            int kk = k0 + c8 * 8;
            uint32_t dst = smem_u32(As + row * 64 + ((c8 ^ (row & 7)) << 3));
            const __half* src = A + (size_t)(bm + row) * lda + kk;
            int sz = (kk < K) ? 16 : 0;
            CP_ASYNC(dst, src, sz);
        }
#pragma unroll
        for (int i = 0; i < NI; i++) {
            int idx = tid + i * 256;
            int row = idx >> 3, c8 = idx & 7;
            int kk = k0 + c8 * 8;
            int n = bn + row;
            int nc = (n < Nd) ? n : (Nd - 1);
            uint32_t dst = smem_u32(Bs + row * 64 + ((c8 ^ (row & 7)) << 3));
            const __half* src = Wt + (size_t)nc * ldw + kk;
            int sz = (n < Nd && kk < K) ? 16 : 0;
            CP_ASYNC(dst, src, sz);
        }
    };

    // ldmatrix lane decomposition
    const int lm = lane >> 3, lr = lane & 7;

    auto compute_tile = [&](int s) {
        const uint32_t sbase = smem_u32(smraw + s * STG);
        const uint32_t a_base = sbase + (uint32_t)(wm * 64 + (lm & 1) * 8 + lr) * 128;
        const int ad = lm >> 1;
        const uint32_t b_base = sbase + 16384u + (uint32_t)(wn * (8 * NI) + (lm >> 1) * 8 + lr) * 128;
        const int bd = lm & 1;
#pragma unroll
        for (int ks = 0; ks < 4; ks++) {
            uint32_t a[4][4], b[NI][2];
#pragma unroll
            for (int mi = 0; mi < 4; mi++) {
                uint32_t addr = a_base + (uint32_t)(mi * 16 * 128) + ((uint32_t)((2 * ks + ad) ^ lr) << 4);
                LDMATRIX_X4(a[mi][0], a[mi][1], a[mi][2], a[mi][3], addr);
            }
#pragma unroll
            for (int np = 0; np < NI / 2; np++) {
                uint32_t addr = b_base + (uint32_t)(np * 16 * 128) + ((uint32_t)((2 * ks + bd) ^ lr) << 4);
                LDMATRIX_X4(b[2 * np][0], b[2 * np][1], b[2 * np + 1][0], b[2 * np + 1][1], addr);
            }
#pragma unroll
            for (int mi = 0; mi < 4; mi++)
#pragma unroll
                for (int ni = 0; ni < NI; ni++)
                    MMA_F16(acc[mi][ni], a[mi], b[ni]);
        }
    };

    // 4-stage pipeline, one __syncthreads per K-tile.
    // Commits before iter kt: min(kt+3, nt). Needed: tile kt complete ->
    // allowed pending = min(kt+3,nt) - kt - 1 = min(2, nt-kt-1).
    {
        int pre = (nt < 3) ? nt : 3;
        for (int i = 0; i < pre; i++) { load_tile(i, i); CP_COMMIT(); }
    }
    for (int kt = 0; kt < nt; kt++) {
        if (kt < nt - 2)       { CP_WAIT(2); }
        else if (kt == nt - 2) { CP_WAIT(1); }
        else                   { CP_WAIT(0); }
        __syncthreads();
        compute_tile(kt & 3);
        if (kt + 3 < nt) {
            load_tile(kt + 3, (kt + 3) & 3);
            CP_COMMIT();
        }
    }

    if (ACT == 5) {
        // fused LSTM-gate epilogue (NI == 8, interleaved layout) + partial add
#pragma unroll
        for (int blk = 0; blk < 2; blk++) {
            const int base = bn + wn * 64 + blk * 32;
            if (base >= Nd) continue;
            const int ub = base >> 5;
            const int u = ub * 8 + 2 * t;
            const int colI = base + 2 * t;
            const float bI0 = bias[colI],      bI1 = bias[colI + 1];
            const float bF0 = bias[colI + 8],  bF1 = bias[colI + 9];
            const float bO0 = bias[colI + 16], bO1 = bias[colI + 17];
            const float bC0 = bias[colI + 24], bC1 = bias[colI + 25];
#pragma unroll
            for (int mi = 0; mi < 4; mi++) {
                const int r0 = bm + wm * 64 + mi * 16 + g;
#pragma unroll
                for (int half_ = 0; half_ < 2; half_++) {
                    const int r = r0 + half_ * 8;
                    const int e0 = half_ * 2, e1 = half_ * 2 + 1;
                    const float* prow = partial + (size_t)r * NG + colI;
                    float2 pI = *(const float2*)(prow);
                    float2 pF = *(const float2*)(prow + 8);
                    float2 pO = *(const float2*)(prow + 16);
                    float2 pC = *(const float2*)(prow + 24);
                    float I0 = sigmoidf_(acc[mi][blk * 4 + 0][e0] + pI.x + bI0);
                    float I1 = sigmoidf_(acc[mi][blk * 4 + 0][e1] + pI.y + bI1);
                    float F0 = sigmoidf_(acc[mi][blk * 4 + 1][e0] + pF.x + bF0);
                    float F1 = sigmoidf_(acc[mi][blk * 4 + 1][e1] + pF.y + bF1);
                    float O0 = sigmoidf_(acc[mi][blk * 4 + 2][e0] + pO.x + bO0);
                    float O1 = sigmoidf_(acc[mi][blk * 4 + 2][e1] + pO.y + bO1);
                    float T0 = tanhf(acc[mi][blk * 4 + 3][e0] + pC.x + bC0);
                    float T1 = tanhf(acc[mi][blk * 4 + 3][e1] + pC.y + bC1);
                    float2 cv = *(const float2*)(cells + (size_t)r * U + u);
                    float c0 = F0 * cv.x + I0 * T0;
                    float c1 = F1 * cv.y + I1 * T1;
                    float hh0 = O0 * tanhf(c0);
                    float hh1 = O1 * tanhf(c1);
                    *(float2*)(outC + (size_t)r * U + u) = make_float2(c0, c1);
                    *(float2*)(outH + (size_t)r * U + u) = make_float2(hh0, hh1);
                    *(__half2*)(outHh + (size_t)r * U + u) = __floats2half2_rn(hh0, hh1);
                }
            }
        }
        return;
    }

#pragma unroll
    for (int ni = 0; ni < NI; ni++) {
        const int col0 = bn + wn * (8 * NI) + ni * 8 + 2 * t;
        if (col0 >= Nd) continue;
        const float b0 = bias ? bias[col0] : 0.f;
        const float b1 = bias ? bias[col0 + 1] : 0.f;
#pragma unroll
        for (int mi = 0; mi < 4; mi++) {
            const int r0 = bm + wm * 64 + mi * 16 + g;
            float v0 = act_apply(acc[mi][ni][0] + b0, ACT);
            float v1 = act_apply(acc[mi][ni][1] + b1, ACT);
            float v2 = act_apply(acc[mi][ni][2] + b0, ACT);
            float v3 = act_apply(acc[mi][ni][3] + b1, ACT);
            if (HOUT) {
                __half* C = (__half*)Cv;
                *(__half2*)(C + (size_t)r0 * ldc + col0)       = __floats2half2_rn(v0, v1);
                *(__half2*)(C + (size_t)(r0 + 8) * ldc + col0) = __floats2half2_rn(v2, v3);
            } else {
                float* C = (float*)Cv;
                *(float2*)(C + (size_t)r0 * ldc + col0)       = make_float2(v0, v1);
                *(float2*)(C + (size_t)(r0 + 8) * ldc + col0) = make_float2(v2, v3);
            }
        }
    }
}

// ================= fast weight transpose + fp16 =================
// W (K,N) f32 -> Wt (N,K) f16. 64x64 tiles, float4 loads, 16B stores.
// PERM: output row = (n>>3)*32 + gate*8 + (n&7)
template <bool PERM>
__global__ void wtrans_k(const float* __restrict__ W, __half* __restrict__ Wt,
                         int K, int N, int gate) {
    __shared__ float ts[64][65];
    const int kb = blockIdx.y * 64, nb = blockIdx.x * 64;
    const int tid = threadIdx.x;
#pragma unroll
    for (int i = 0; i < 4; i++) {
        int idx = tid + i * 256;
        int k = idx >> 4, q = idx & 15;
        int gk = kb + k, gn = nb + q * 4;
        float4 v = make_float4(0.f, 0.f, 0.f, 0.f);
        if (gk < K && gn < N) v = *(const float4*)(W + (size_t)gk * N + gn);
        ts[k][q * 4 + 0] = v.x;
        ts[k][q * 4 + 1] = v.y;
        ts[k][q * 4 + 2] = v.z;
        ts[k][q * 4 + 3] = v.w;
    }
    __syncthreads();
#pragma unroll
    for (int i = 0; i < 2; i++) {
        int idx = tid + i * 256;
        int n = idx >> 3, c = idx & 7;
        int gn = nb + n;
        int gk = kb + c * 8;
        if (gn >= N || gk >= K) continue;
        __half hv[8];
#pragma unroll
        for (int j = 0; j < 8; j++) hv[j] = __float2half_rn(ts[c * 8 + j][n]);
        int row = PERM ? (((gn >> 3) << 5) + gate * 8 + (gn & 7)) : gn;
        *(uint4*)(Wt + (size_t)row * K + gk) = *(uint4*)hv;
    }
}

// ================= pointwise kernels =================
__global__ void transpose_z_k(const float* __restrict__ z, __half* __restrict__ zb) {
    int idx = blockIdx.x * blockDim.x + threadIdx.x;
    if (idx >= ROWS * DT) return;
    int bn = idx / DT;
    int rem = idx - bn * DT;
    int d = rem / Tt;
    int t = rem - d * Tt;
    int b = bn >> 3;
    int n = bn & 7;
    zb[idx] = __float2half_rn(z[((size_t)(b * Tt + t) * Ns + n) * Dd + d]);
}

__global__ void round_copy_k(const float* __restrict__ src, __half* __restrict__ dst, int n) {
    int idx = blockIdx.x * blockDim.x + threadIdx.x;
    if (idx >= n) return;
    dst[idx] = __float2half_rn(src[idx]);
}

__global__ void fuse_bias_perm_k(const float* __restrict__ bI, const float* __restrict__ bF,
                                 const float* __restrict__ bO, const float* __restrict__ bC,
                                 float* __restrict__ dst) {
    int idx = blockIdx.x * blockDim.x + threadIdx.x;
    if (idx >= NG) return;
    int gate = idx / U, u = idx - gate * U;
    const float* src = (gate == 0) ? bI : (gate == 1) ? bF : (gate == 2) ? bO : bC;
    dst[((u >> 3) << 5) + gate * 8 + (u & 7)] = src[u];
}

__global__ void pair_combine_k(const __half* __restrict__ ai, int ldi,
                               const __half* __restrict__ aj, int ldj,
                               const float* __restrict__ bias, __half* __restrict__ out) {
    int idx = blockIdx.x * blockDim.x + threadIdx.x;   // over PROWS * (H/2)
    if (idx >= PROWS * (H / 2)) return;
    int row = idx / (H / 2);
    int h2 = idx - row * (H / 2);
    int j = row & 7;
    int i_row = row >> 3;
    int b = i_row >> 3;
    int j_row = (b << 3) + j;

    float2 a = __half22float2(*((const __half2*)(ai + (size_t)i_row * ldi) + h2));
    float2 c = __half22float2(*((const __half2*)(aj + (size_t)j_row * ldj) + h2));
    float2 bb = ((const float2*)bias)[h2];
    float o0 = act_apply(a.x + c.x + bb.x, 2);
    float o1 = act_apply(a.y + c.y + bb.y, 2);
    ((__half2*)(out + (size_t)row * H))[h2] = __floats2half2_rn(o0, o1);
}

__global__ void reduce_inter_k(const __half* __restrict__ rA, const __half* __restrict__ rB,
                               __half* __restrict__ xh) {
    int idx = blockIdx.x * blockDim.x + threadIdx.x;   // over ROWS * (H/2)
    if (idx >= ROWS * (H / 2)) return;
    int row = idx / (H / 2);
    int h2 = idx - row * (H / 2);
    float s0 = 0.f, s1 = 0.f, m0 = -INFINITY, m1 = -INFINITY;
#pragma unroll
    for (int j = 0; j < Ns; j++) {
        size_t p = (size_t)(row * Ns + j) * (H / 2) + h2;
        float2 va = __half22float2(((const __half2*)rA)[p]);
        float2 vb = __half22float2(((const __half2*)rB)[p]);
        float v0 = va.x + vb.x, v1 = va.y + vb.y;
        s0 += v0; s1 += v1;
        m0 = fmaxf(m0, v0); m1 = fmaxf(m1, v1);
    }
    __half* base = xh + (size_t)row * GIN;
    *(__half2*)(base + BUF + 2 * h2)     = __floats2half2_rn(s0, s1);
    *(__half2*)(base + BUF + H + 2 * h2) = __floats2half2_rn(m0, m1);
}

__global__ void copy_hidden_k(const float* __restrict__ hidden, __half* __restrict__ xh) {
    int idx = blockIdx.x * blockDim.x + threadIdx.x;   // over ROWS * (U/2)
    if (idx >= ROWS * (U / 2)) return;
    int row = idx / (U / 2);
    int c2 = idx - row * (U / 2);
    float2 v = ((const float2*)(hidden + (size_t)row * U))[c2];
    *(__half2*)(xh + (size_t)row * GIN + XDIM + 2 * c2) = __floats2half2_rn(v.x, v.y);
}

// ================= host =================
template <int ACT, bool HOUT, int NI>
static void launch_hg(cudaStream_t st,
                      const __half* A, int lda, const __half* Wt, int ldw,
                      const float* bias,
                      void* C, int ldc, int M, int Nd, int K,
                      const float* partial = nullptr,
                      const float* cells = nullptr, float* outC = nullptr,
                      float* outH = nullptr, __half* outHh = nullptr) {
    constexpr int BN = 32 * NI;
    constexpr int smem = 4 * ((128 + BN) * 64 * 2);
    cudaFuncSetAttribute(hgemm<ACT, HOUT, NI>, cudaFuncAttributeMaxDynamicSharedMemorySize, smem);
    dim3 grid((Nd + BN - 1) / BN, M / 128);
    hgemm<ACT, HOUT, NI><<<grid, 256, smem, st>>>(A, lda, Wt, ldw, bias, C, ldc, M, Nd, K,
                                                  partial, cells, outC, outH, outHh);
}

template <bool PERM>
static void launch_wtrans(cudaStream_t st, const float* W, __half* Wt, int K, int N, int gate = 0) {
    dim3 grid((N + 63) / 64, (K + 63) / 64);
    wtrans_k<PERM><<<grid, 256, 0, st>>>(W, Wt, K, N, gate);
}

// Persistent stream/event pool (created once on the pre-baseline correctness
// run; reused by every captured call; never destroyed).
namespace {
struct StreamPool {
    cudaStream_t s1, s2;
    cudaEvent_t evFork, evS1, evProj, evBl, evS2;
    StreamPool() {
        cudaStreamCreateWithFlags(&s1, cudaStreamNonBlocking);
        cudaStreamCreateWithFlags(&s2, cudaStreamNonBlocking);
        cudaEventCreateWithFlags(&evFork, cudaEventDisableTiming);
        cudaEventCreateWithFlags(&evS1,   cudaEventDisableTiming);
        cudaEventCreateWithFlags(&evProj, cudaEventDisableTiming);
        cudaEventCreateWithFlags(&evBl,   cudaEventDisableTiming);
        cudaEventCreateWithFlags(&evS2,   cudaEventDisableTiming);
    }
};
}

extern "C" void kernel_launch(void* const* d_in, const int* in_sizes, int n_in,
                              void* d_out, int out_size) {
    const float* z      = (const float*)d_in[0];
    const float* Cells  = (const float*)d_in[1];
    const float* hidden = (const float*)d_in[2];
    const float* W_buf  = (const float*)d_in[3];
    const float* b_buf  = (const float*)d_in[4];
    const float* W_r1   = (const float*)d_in[5];
    const float* b_r1   = (const float*)d_in[6];
    const float* W_r2   = (const float*)d_in[7];
    const float* b_r2   = (const float*)d_in[8];
    const float* W_r3   = (const float*)d_in[9];
    const float* b_r3   = (const float*)d_in[10];
    const float* W_l1   = (const float*)d_in[11];
    const float* b_l1   = (const float*)d_in[12];
    const float* W_l2   = (const float*)d_in[13];
    const float* b_l2   = (const float*)d_in[14];
    const float* W_l3   = (const float*)d_in[15];
    const float* b_l3   = (const float*)d_in[16];
    const float* W_I    = (const float*)d_in[17];
    const float* b_I    = (const float*)d_in[18];
    const float* W_F    = (const float*)d_in[19];
    const float* b_F    = (const float*)d_in[20];
    const float* W_O    = (const float*)d_in[21];
    const float* b_O    = (const float*)d_in[22];
    const float* W_C    = (const float*)d_in[23];
    const float* b_C    = (const float*)d_in[24];
    const float* W_d    = (const float*)d_in[25];
    const float* b_d    = (const float*)d_in[26];

    float* out = (float*)d_out;

    __half *wt, *zb, *cellsH, *proj, *bl, *rA, *rB, *rC, *rD, *xh, *hnewH;
    float *biasG, *gpart;
    cudaGetSymbolAddress((void**)&wt, h_wt);
    cudaGetSymbolAddress((void**)&zb, h_zb);
    cudaGetSymbolAddress((void**)&cellsH, h_cells);
    cudaGetSymbolAddress((void**)&proj, h_proj);
    cudaGetSymbolAddress((void**)&bl, h_bl);
    cudaGetSymbolAddress((void**)&rA, h_rA);
    cudaGetSymbolAddress((void**)&rB, h_rB);
    cudaGetSymbolAddress((void**)&rC, h_rC);
    cudaGetSymbolAddress((void**)&rD, h_rD);
    cudaGetSymbolAddress((void**)&xh, h_xh);
    cudaGetSymbolAddress((void**)&hnewH, h_hnew);
    cudaGetSymbolAddress((void**)&biasG, g_bias);
    cudaGetSymbolAddress((void**)&gpart, g_part);

    static StreamPool pool;
    cudaStream_t s1 = pool.s1, s2 = pool.s2;
    cudaStream_t m = 0;       // capturing (legacy) stream

    cudaEventRecord(pool.evFork, m);

    // ---- s1: gate weights (full-K transposes) + hidden-slice partial gate GEMM
    cudaStreamWaitEvent(s1, pool.evFork, 0);
    launch_wtrans<true>(s1, W_I, wt + OFF_G, GIN, U, 0);
    launch_wtrans<true>(s1, W_F, wt + OFF_G, GIN, U, 1);
    launch_wtrans<true>(s1, W_O, wt + OFF_G, GIN, U, 2);
    launch_wtrans<true>(s1, W_C, wt + OFF_G, GIN, U, 3);
    fuse_bias_perm_k<<<(NG + 255) / 256, 256, 0, s1>>>(b_I, b_F, b_O, b_C, biasG);
    copy_hidden_k<<<(ROWS * (U / 2) + 255) / 256, 256, 0, s1>>>(hidden, xh);
    // pass 1: gpart = xh[:, XDIM:] @ Wg[:, XDIM:]^T  (K = U)
    launch_hg<0, false, 8>(s1, xh + XDIM, GIN, wt + OFF_G + XDIM, GIN, nullptr,
                           gpart, NG, ROWS, NG, U);
    cudaEventRecord(pool.evS1, s1);

    // ---- s2: projection path (concurrent with main's buffer GEMM)
    cudaStreamWaitEvent(s2, pool.evFork, 0);
    launch_wtrans<false>(s2, W_r1,                 wt + OFF_R1A, U, H);
    launch_wtrans<false>(s2, W_r1 + (size_t)U * H, wt + OFF_R1B, U, H);
    launch_wtrans<false>(s2, W_l1,                 wt + OFF_L1A, U, H);
    round_copy_k<<<(ROWS * U + 255) / 256, 256, 0, s2>>>(Cells, cellsH, ROWS * U);
    launch_hg<0, true, 4>(s2, cellsH, U, wt + OFF_R1A, U, nullptr, proj, 1536, ROWS, 1536, U);
    cudaEventRecord(pool.evProj, s2);
    launch_wtrans<false>(s2, W_l2, wt + OFF_L2, H, H);
    launch_wtrans<false>(s2, W_l3, wt + OFF_L3, H, H);

    // ---- main: buffer path FIRST (critical for evBl), deferred small wtrans after
    transpose_z_k<<<(ROWS * DT + 255) / 256, 256, 0, m>>>(z, zb);
    launch_wtrans<false>(m, W_buf, wt + OFF_BUF, DT, BUF);
    launch_wtrans<false>(m, W_l1 + (size_t)U * H, wt + OFF_L1B, BUF, H);
    launch_hg<1, true, 4>(m, zb, DT, wt + OFF_BUF, DT, b_buf, xh, GIN, ROWS, BUF, DT);
    launch_hg<0, true, 4>(m, xh, GIN, wt + OFF_L1B, BUF, nullptr, bl, H, ROWS, H, BUF);
    cudaEventRecord(pool.evBl, m);
    launch_wtrans<false>(m, W_r2, wt + OFF_R2, H, H);
    launch_wtrans<false>(m, W_r3, wt + OFF_R3, H, H);
    launch_wtrans<false>(m, W_d, wt + OFF_D, U, Dd);

    // ---- s2: lambda path (combine -> rC, l2 -> rD, l3 -> rC)
    cudaStreamWaitEvent(s2, pool.evBl, 0);
    pair_combine_k<<<(PROWS * (H / 2) + 255) / 256, 256, 0, s2>>>(proj + 1024, 1536, bl, H, b_l1, rC);
    launch_hg<2, true, 8>(s2, rC, H, wt + OFF_L2, H, b_l2, rD, H, PROWS, H, H);
    launch_hg<2, true, 8>(s2, rD, H, wt + OFF_L3, H, b_l3, rC, H, PROWS, H, H);
    cudaEventRecord(pool.evS2, s2);

    // ---- main: rho path (combine -> rA, r2 -> rB, r3 -> rA)
    cudaStreamWaitEvent(m, pool.evProj, 0);
    pair_combine_k<<<(PROWS * (H / 2) + 255) / 256, 256, 0, m>>>(proj, 1536, proj + 512, 1536, b_r1, rA);
    launch_hg<2, true, 8>(m, rA, H, wt + OFF_R2, H, b_r2, rB, H, PROWS, H, H);
    launch_hg<2, true, 8>(m, rB, H, wt + OFF_R3, H, b_r3, rA, H, PROWS, H, H);

    // ---- join: reduce, then final gate pass (K = XDIM) with fused LSTM epilogue
    cudaStreamWaitEvent(m, pool.evS2, 0);
    reduce_inter_k<<<(ROWS * (H / 2) + 255) / 256, 256, 0, m>>>(rA, rC, xh);
    cudaStreamWaitEvent(m, pool.evS1, 0);
    launch_hg<5, false, 8>(m, xh, GIN, wt + OFF_G, GIN, biasG,
                           nullptr, 0, ROWS, NG, XDIM,
                           gpart, Cells, out + OUT_OFF_C, out + OUT_OFF_H, hnewH);

    // ---- decode
    launch_hg<0, false, 4>(m, hnewH, U, wt + OFF_D, U, b_d, out, Dd, ROWS, Dd, U);
}

// round 14
// speedup vs baseline: 1.5033x; 1.0155x over previous
#include <cuda_runtime.h>
#include <cuda_fp16.h>
#include <math.h>
#include <stdint.h>

// ================= problem constants =================
namespace {
constexpr int Bb   = 256;
constexpr int Tt   = 15;
constexpr int Ns   = 8;
constexpr int Dd   = 64;
constexpr int U    = 2056;
constexpr int H    = 512;
constexpr int BUF  = 1680;
constexpr int XDIM = BUF + 2 * H;   // 2704
constexpr int GIN  = XDIM + U;      // 4760
constexpr int ROWS = Bb * Ns;       // 2048
constexpr int PROWS = ROWS * Ns;    // 16384
constexpr int DT   = Dd * Tt;       // 960
constexpr int NG   = 4 * U;         // 8224 fused (interleaved) gate width
constexpr int OUT_OFF_C   = ROWS * Dd;
constexpr int OUT_OFF_H   = OUT_OFF_C + ROWS * U;
constexpr int DSZ  = ROWS * Dd;     // decode partial slice size

// transposed-weight scratch offsets (halfs)
constexpr size_t OFF_BUF = 0;                                 // 1680 x 960
constexpr size_t OFF_R1A = OFF_BUF + (size_t)1680 * 960;      // 512 x 2056 (fused x3)
constexpr size_t OFF_R1B = OFF_R1A + (size_t)512 * 2056;
constexpr size_t OFF_L1A = OFF_R1B + (size_t)512 * 2056;
constexpr size_t OFF_L1B = OFF_L1A + (size_t)512 * 2056;      // 512 x 1680
constexpr size_t OFF_R2  = OFF_L1B + (size_t)512 * 1680;      // 512 x 512
constexpr size_t OFF_R3  = OFF_R2 + (size_t)512 * 512;
constexpr size_t OFF_L2  = OFF_R3 + (size_t)512 * 512;
constexpr size_t OFF_L3  = OFF_L2 + (size_t)512 * 512;
constexpr size_t OFF_G   = OFF_L3 + (size_t)512 * 512;        // 8224 x 4760 interleaved gates
constexpr size_t OFF_D   = OFF_G + (size_t)NG * 4760;         // 64 x 2056
constexpr size_t WT_TOTAL = OFF_D + (size_t)64 * 2056;
}

// ================= scratch (static device memory) =================
__device__ __half h_wt[WT_TOTAL];
__device__ __half h_zb[ROWS * DT];
__device__ __half h_cells[ROWS * U];
__device__ __half h_proj[ROWS * 1536];          // [ai | aj | al]
__device__ __half h_bl[ROWS * H];
__device__ __half h_rA[(size_t)PROWS * H];
__device__ __half h_rB[(size_t)PROWS * H];
__device__ __half h_rC[(size_t)PROWS * H];
__device__ __half h_rD[(size_t)PROWS * H];
__device__ __half h_xh[(size_t)ROWS * GIN];
__device__ __half h_hnew[ROWS * U];
__device__ float  g_part[(size_t)ROWS * NG];    // hidden-slice partial gate sums
__device__ float  g_dec[4 * DSZ];               // split-K decode partials
__device__ float  g_bias[NG];

// ================= helpers =================
__device__ __forceinline__ uint32_t smem_u32(const void* p) {
    uint32_t a;
    asm("{ .reg .u64 t; cvta.to.shared.u64 t, %1; cvt.u32.u64 %0, t; }" : "=r"(a) : "l"(p));
    return a;
}

#define CP_ASYNC(dst, src, sz) \
    asm volatile("cp.async.cg.shared.global [%0], [%1], 16, %2;" \
        :: "r"(dst), "l"(src), "r"(sz))
#define CP_COMMIT() asm volatile("cp.async.commit_group;" ::: "memory")
#define CP_WAIT(N)  asm volatile("cp.async.wait_group %0;" :: "n"(N) : "memory")

#define MMA_F16(d, a, b) \
    asm volatile("mma.sync.aligned.m16n8k16.row.col.f32.f16.f16.f32 " \
        "{%0,%1,%2,%3}, {%4,%5,%6,%7}, {%8,%9}, {%0,%1,%2,%3};" \
        : "+f"((d)[0]), "+f"((d)[1]), "+f"((d)[2]), "+f"((d)[3]) \
        : "r"((a)[0]), "r"((a)[1]), "r"((a)[2]), "r"((a)[3]), \
          "r"((b)[0]), "r"((b)[1]))

#define LDMATRIX_X4(r0, r1, r2, r3, addr) \
    asm volatile("ldmatrix.sync.aligned.m8n8.x4.shared.b16 {%0,%1,%2,%3}, [%4];" \
        : "=r"(r0), "=r"(r1), "=r"(r2), "=r"(r3) : "r"(addr))

// ================= activations =================
// ACT: 0 none, 1 elu, 2 gelu, 3 sigmoid, 4 tanh, 5 fused-gate epilogue (w/ partial)
__device__ __forceinline__ float act_apply(float x, int ACT) {
    if (ACT == 1) return x > 0.f ? x : expm1f(x);
    if (ACT == 2) return 0.5f * x * (1.f + erff(x * 0.70710678118654752440f));
    if (ACT == 3) return 1.f / (1.f + expf(-x));
    if (ACT == 4) return tanhf(x);
    return x;
}
__device__ __forceinline__ float sigmoidf_(float x) { return 1.f / (1.f + expf(-x)); }

// ================= fp16 mma GEMM (4-stage cp.async + ldmatrix) =================
// C = act(A @ Wt^T + bias). A: (M,K) halfs stride lda. Wt: (Nd,K) halfs stride ldw.
// CTA tile 128 x (32*NI) x 64. 256 thr, 8 warps (2m x 4n), warp tile 64 x (8*NI).
// ACT==5 (NI==8): interleaved-gate LSTM epilogue, adds `partial` before activation.
template <int ACT, bool HOUT, int NI>
__global__ void __launch_bounds__(256, 1)
hgemm(const __half* __restrict__ A, int lda,
      const __half* __restrict__ Wt, int ldw,
      const float* __restrict__ bias,
      void* __restrict__ Cv, int ldc,
      int M, int Nd, int K,
      const float* __restrict__ partial,
      const float* __restrict__ cells,
      float* __restrict__ outC,
      float* __restrict__ outH,
      __half* __restrict__ outHh) {
    constexpr int BN = 32 * NI;
    constexpr int STG = (128 + BN) * 64 * 2;     // bytes per stage
    extern __shared__ __align__(16) char smraw[];

    const int tid = threadIdx.x;
    const int lane = tid & 31;
    const int wid = tid >> 5;
    const int g = lane >> 2, t = lane & 3;
    const int wm = wid >> 2, wn = wid & 3;
    const int bm = blockIdx.y * 128, bn = blockIdx.x * BN;

    float acc[4][NI][4];
#pragma unroll
    for (int i = 0; i < 4; i++)
#pragma unroll
        for (int j = 0; j < NI; j++)
#pragma unroll
            for (int q = 0; q < 4; q++) acc[i][j][q] = 0.f;

    const int nt = (K + 63) / 64;

    auto load_tile = [&](int kt, int s) {
        __half* As = (__half*)(smraw + s * STG);
        __half* Bs = As + 8192;
        const int k0 = kt * 64;
#pragma unroll
        for (int i = 0; i < 4; i++) {
            int idx = tid + i * 256;
            int row = idx >> 3, c8 = idx & 7;
            int kk = k0 + c8 * 8;
            uint32_t dst = smem_u32(As + row * 64 + ((c8 ^ (row & 7)) << 3));
            const __half* src = A + (size_t)(bm + row) * lda + kk;
            int sz = (kk < K) ? 16 : 0;
            CP_ASYNC(dst, src, sz);
        }
#pragma unroll
        for (int i = 0; i < NI; i++) {
            int idx = tid + i * 256;
            int row = idx >> 3, c8 = idx & 7;
            int kk = k0 + c8 * 8;
            int n = bn + row;
            int nc = (n < Nd) ? n : (Nd - 1);
            uint32_t dst = smem_u32(Bs + row * 64 + ((c8 ^ (row & 7)) << 3));
            const __half* src = Wt + (size_t)nc * ldw + kk;
            int sz = (n < Nd && kk < K) ? 16 : 0;
            CP_ASYNC(dst, src, sz);
        }
    };

    // ldmatrix lane decomposition
    const int lm = lane >> 3, lr = lane & 7;

    auto compute_tile = [&](int s) {
        const uint32_t sbase = smem_u32(smraw + s * STG);
        const uint32_t a_base = sbase + (uint32_t)(wm * 64 + (lm & 1) * 8 + lr) * 128;
        const int ad = lm >> 1;
        const uint32_t b_base = sbase + 16384u + (uint32_t)(wn * (8 * NI) + (lm >> 1) * 8 + lr) * 128;
        const int bd = lm & 1;
#pragma unroll
        for (int ks = 0; ks < 4; ks++) {
            uint32_t a[4][4], b[NI][2];
#pragma unroll
            for (int mi = 0; mi < 4; mi++) {
                uint32_t addr = a_base + (uint32_t)(mi * 16 * 128) + ((uint32_t)((2 * ks + ad) ^ lr) << 4);
                LDMATRIX_X4(a[mi][0], a[mi][1], a[mi][2], a[mi][3], addr);
            }
#pragma unroll
            for (int np = 0; np < NI / 2; np++) {
                uint32_t addr = b_base + (uint32_t)(np * 16 * 128) + ((uint32_t)((2 * ks + bd) ^ lr) << 4);
                LDMATRIX_X4(b[2 * np][0], b[2 * np][1], b[2 * np + 1][0], b[2 * np + 1][1], addr);
            }
#pragma unroll
            for (int mi = 0; mi < 4; mi++)
#pragma unroll
                for (int ni = 0; ni < NI; ni++)
                    MMA_F16(acc[mi][ni], a[mi], b[ni]);
        }
    };

    // 4-stage pipeline, one __syncthreads per K-tile.
    {
        int pre = (nt < 3) ? nt : 3;
        for (int i = 0; i < pre; i++) { load_tile(i, i); CP_COMMIT(); }
    }
    for (int kt = 0; kt < nt; kt++) {
        if (kt < nt - 2)       { CP_WAIT(2); }
        else if (kt == nt - 2) { CP_WAIT(1); }
        else                   { CP_WAIT(0); }
        __syncthreads();
        compute_tile(kt & 3);
        if (kt + 3 < nt) {
            load_tile(kt + 3, (kt + 3) & 3);
            CP_COMMIT();
        }
    }

    if (ACT == 5) {
        // fused LSTM-gate epilogue (NI == 8, interleaved layout) + partial add
#pragma unroll
        for (int blk = 0; blk < 2; blk++) {
            const int base = bn + wn * 64 + blk * 32;
            if (base >= Nd) continue;
            const int ub = base >> 5;
            const int u = ub * 8 + 2 * t;
            const int colI = base + 2 * t;
            const float bI0 = bias[colI],      bI1 = bias[colI + 1];
            const float bF0 = bias[colI + 8],  bF1 = bias[colI + 9];
            const float bO0 = bias[colI + 16], bO1 = bias[colI + 17];
            const float bC0 = bias[colI + 24], bC1 = bias[colI + 25];
#pragma unroll
            for (int mi = 0; mi < 4; mi++) {
                const int r0 = bm + wm * 64 + mi * 16 + g;
#pragma unroll
                for (int half_ = 0; half_ < 2; half_++) {
                    const int r = r0 + half_ * 8;
                    const int e0 = half_ * 2, e1 = half_ * 2 + 1;
                    const float* prow = partial + (size_t)r * NG + colI;
                    float2 pI = *(const float2*)(prow);
                    float2 pF = *(const float2*)(prow + 8);
                    float2 pO = *(const float2*)(prow + 16);
                    float2 pC = *(const float2*)(prow + 24);
                    float I0 = sigmoidf_(acc[mi][blk * 4 + 0][e0] + pI.x + bI0);
                    float I1 = sigmoidf_(acc[mi][blk * 4 + 0][e1] + pI.y + bI1);
                    float F0 = sigmoidf_(acc[mi][blk * 4 + 1][e0] + pF.x + bF0);
                    float F1 = sigmoidf_(acc[mi][blk * 4 + 1][e1] + pF.y + bF1);
                    float O0 = sigmoidf_(acc[mi][blk * 4 + 2][e0] + pO.x + bO0);
                    float O1 = sigmoidf_(acc[mi][blk * 4 + 2][e1] + pO.y + bO1);
                    float T0 = tanhf(acc[mi][blk * 4 + 3][e0] + pC.x + bC0);
                    float T1 = tanhf(acc[mi][blk * 4 + 3][e1] + pC.y + bC1);
                    float2 cv = *(const float2*)(cells + (size_t)r * U + u);
                    float c0 = F0 * cv.x + I0 * T0;
                    float c1 = F1 * cv.y + I1 * T1;
                    float hh0 = O0 * tanhf(c0);
                    float hh1 = O1 * tanhf(c1);
                    *(float2*)(outC + (size_t)r * U + u) = make_float2(c0, c1);
                    *(float2*)(outH + (size_t)r * U + u) = make_float2(hh0, hh1);
                    *(__half2*)(outHh + (size_t)r * U + u) = __floats2half2_rn(hh0, hh1);
                }
            }
        }
        return;
    }

#pragma unroll
    for (int ni = 0; ni < NI; ni++) {
        const int col0 = bn + wn * (8 * NI) + ni * 8 + 2 * t;
        if (col0 >= Nd) continue;
        const float b0 = bias ? bias[col0] : 0.f;
        const float b1 = bias ? bias[col0 + 1] : 0.f;
#pragma unroll
        for (int mi = 0; mi < 4; mi++) {
            const int r0 = bm + wm * 64 + mi * 16 + g;
            float v0 = act_apply(acc[mi][ni][0] + b0, ACT);
            float v1 = act_apply(acc[mi][ni][1] + b1, ACT);
            float v2 = act_apply(acc[mi][ni][2] + b0, ACT);
            float v3 = act_apply(acc[mi][ni][3] + b1, ACT);
            if (HOUT) {
                __half* C = (__half*)Cv;
                *(__half2*)(C + (size_t)r0 * ldc + col0)       = __floats2half2_rn(v0, v1);
                *(__half2*)(C + (size_t)(r0 + 8) * ldc + col0) = __floats2half2_rn(v2, v3);
            } else {
                float* C = (float*)Cv;
                *(float2*)(C + (size_t)r0 * ldc + col0)       = make_float2(v0, v1);
                *(float2*)(C + (size_t)(r0 + 8) * ldc + col0) = make_float2(v2, v3);
            }
        }
    }
}

// ================= fast weight transpose + fp16 =================
// W (K,N) f32 -> Wt (N,K) f16. 64x64 tiles, float4 loads, 16B stores.
// PERM: output row = (n>>3)*32 + gate*8 + (n&7)
template <bool PERM>
__global__ void wtrans_k(const float* __restrict__ W, __half* __restrict__ Wt,
                         int K, int N, int gate) {
    __shared__ float ts[64][65];
    const int kb = blockIdx.y * 64, nb = blockIdx.x * 64;
    const int tid = threadIdx.x;
#pragma unroll
    for (int i = 0; i < 4; i++) {
        int idx = tid + i * 256;
        int k = idx >> 4, q = idx & 15;
        int gk = kb + k, gn = nb + q * 4;
        float4 v = make_float4(0.f, 0.f, 0.f, 0.f);
        if (gk < K && gn < N) v = *(const float4*)(W + (size_t)gk * N + gn);
        ts[k][q * 4 + 0] = v.x;
        ts[k][q * 4 + 1] = v.y;
        ts[k][q * 4 + 2] = v.z;
        ts[k][q * 4 + 3] = v.w;
    }
    __syncthreads();
#pragma unroll
    for (int i = 0; i < 2; i++) {
        int idx = tid + i * 256;
        int n = idx >> 3, c = idx & 7;
        int gn = nb + n;
        int gk = kb + c * 8;
        if (gn >= N || gk >= K) continue;
        __half hv[8];
#pragma unroll
        for (int j = 0; j < 8; j++) hv[j] = __float2half_rn(ts[c * 8 + j][n]);
        int row = PERM ? (((gn >> 3) << 5) + gate * 8 + (gn & 7)) : gn;
        *(uint4*)(Wt + (size_t)row * K + gk) = *(uint4*)hv;
    }
}

// ================= pointwise kernels =================
__global__ void transpose_z_k(const float* __restrict__ z, __half* __restrict__ zb) {
    int idx = blockIdx.x * blockDim.x + threadIdx.x;
    if (idx >= ROWS * DT) return;
    int bn = idx / DT;
    int rem = idx - bn * DT;
    int d = rem / Tt;
    int t = rem - d * Tt;
    int b = bn >> 3;
    int n = bn & 7;
    zb[idx] = __float2half_rn(z[((size_t)(b * Tt + t) * Ns + n) * Dd + d]);
}

__global__ void round_copy_k(const float* __restrict__ src, __half* __restrict__ dst, int n) {
    int idx = blockIdx.x * blockDim.x + threadIdx.x;
    if (idx >= n) return;
    dst[idx] = __float2half_rn(src[idx]);
}

__global__ void fuse_bias_perm_k(const float* __restrict__ bI, const float* __restrict__ bF,
                                 const float* __restrict__ bO, const float* __restrict__ bC,
                                 float* __restrict__ dst) {
    int idx = blockIdx.x * blockDim.x + threadIdx.x;
    if (idx >= NG) return;
    int gate = idx / U, u = idx - gate * U;
    const float* src = (gate == 0) ? bI : (gate == 1) ? bF : (gate == 2) ? bO : bC;
    dst[((u >> 3) << 5) + gate * 8 + (u & 7)] = src[u];
}

__global__ void pair_combine_k(const __half* __restrict__ ai, int ldi,
                               const __half* __restrict__ aj, int ldj,
                               const float* __restrict__ bias, __half* __restrict__ out) {
    int idx = blockIdx.x * blockDim.x + threadIdx.x;   // over PROWS * (H/2)
    if (idx >= PROWS * (H / 2)) return;
    int row = idx / (H / 2);
    int h2 = idx - row * (H / 2);
    int j = row & 7;
    int i_row = row >> 3;
    int b = i_row >> 3;
    int j_row = (b << 3) + j;

    float2 a = __half22float2(*((const __half2*)(ai + (size_t)i_row * ldi) + h2));
    float2 c = __half22float2(*((const __half2*)(aj + (size_t)j_row * ldj) + h2));
    float2 bb = ((const float2*)bias)[h2];
    float o0 = act_apply(a.x + c.x + bb.x, 2);
    float o1 = act_apply(a.y + c.y + bb.y, 2);
    ((__half2*)(out + (size_t)row * H))[h2] = __floats2half2_rn(o0, o1);
}

__global__ void reduce_inter_k(const __half* __restrict__ rA, const __half* __restrict__ rB,
                               __half* __restrict__ xh) {
    int idx = blockIdx.x * blockDim.x + threadIdx.x;   // over ROWS * (H/2)
    if (idx >= ROWS * (H / 2)) return;
    int row = idx / (H / 2);
    int h2 = idx - row * (H / 2);
    float s0 = 0.f, s1 = 0.f, m0 = -INFINITY, m1 = -INFINITY;
#pragma unroll
    for (int j = 0; j < Ns; j++) {
        size_t p = (size_t)(row * Ns + j) * (H / 2) + h2;
        float2 va = __half22float2(((const __half2*)rA)[p]);
        float2 vb = __half22float2(((const __half2*)rB)[p]);
        float v0 = va.x + vb.x, v1 = va.y + vb.y;
        s0 += v0; s1 += v1;
        m0 = fmaxf(m0, v0); m1 = fmaxf(m1, v1);
    }
    __half* base = xh + (size_t)row * GIN;
    *(__half2*)(base + BUF + 2 * h2)     = __floats2half2_rn(s0, s1);
    *(__half2*)(base + BUF + H + 2 * h2) = __floats2half2_rn(m0, m1);
}

__global__ void copy_hidden_k(const float* __restrict__ hidden, __half* __restrict__ xh) {
    int idx = blockIdx.x * blockDim.x + threadIdx.x;   // over ROWS * (U/2)
    if (idx >= ROWS * (U / 2)) return;
    int row = idx / (U / 2);
    int c2 = idx - row * (U / 2);
    float2 v = ((const float2*)(hidden + (size_t)row * U))[c2];
    *(__half2*)(xh + (size_t)row * GIN + XDIM + 2 * c2) = __floats2half2_rn(v.x, v.y);
}

__global__ void decode_sum_k(const float* __restrict__ p, const float* __restrict__ bias,
                             float* __restrict__ out) {
    int idx = blockIdx.x * blockDim.x + threadIdx.x;   // over DSZ
    if (idx >= DSZ) return;
    int col = idx & (Dd - 1);
    out[idx] = ((p[idx] + p[DSZ + idx]) + (p[2 * DSZ + idx] + p[3 * DSZ + idx])) + bias[col];
}

// ================= host =================
template <int ACT, bool HOUT, int NI>
static void launch_hg(cudaStream_t st,
                      const __half* A, int lda, const __half* Wt, int ldw,
                      const float* bias,
                      void* C, int ldc, int M, int Nd, int K,
                      const float* partial = nullptr,
                      const float* cells = nullptr, float* outC = nullptr,
                      float* outH = nullptr, __half* outHh = nullptr) {
    constexpr int BN = 32 * NI;
    constexpr int smem = 4 * ((128 + BN) * 64 * 2);
    cudaFuncSetAttribute(hgemm<ACT, HOUT, NI>, cudaFuncAttributeMaxDynamicSharedMemorySize, smem);
    dim3 grid((Nd + BN - 1) / BN, M / 128);
    hgemm<ACT, HOUT, NI><<<grid, 256, smem, st>>>(A, lda, Wt, ldw, bias, C, ldc, M, Nd, K,
                                                  partial, cells, outC, outH, outHh);
}

template <bool PERM>
static void launch_wtrans(cudaStream_t st, const float* W, __half* Wt, int K, int N, int gate = 0) {
    dim3 grid((N + 63) / 64, (K + 63) / 64);
    wtrans_k<PERM><<<grid, 256, 0, st>>>(W, Wt, K, N, gate);
}

// Persistent stream/event pool (created once on the pre-baseline correctness
// run; reused by every captured call; never destroyed).
namespace {
struct StreamPool {
    cudaStream_t s1, s2, s3;
    cudaEvent_t evFork, evS1, evProj, evBl, evS2, evGate, evD1, evD2, evD3;
    StreamPool() {
        cudaStreamCreateWithFlags(&s1, cudaStreamNonBlocking);
        cudaStreamCreateWithFlags(&s2, cudaStreamNonBlocking);
        cudaStreamCreateWithFlags(&s3, cudaStreamNonBlocking);
        cudaEventCreateWithFlags(&evFork, cudaEventDisableTiming);
        cudaEventCreateWithFlags(&evS1,   cudaEventDisableTiming);
        cudaEventCreateWithFlags(&evProj, cudaEventDisableTiming);
        cudaEventCreateWithFlags(&evBl,   cudaEventDisableTiming);
        cudaEventCreateWithFlags(&evS2,   cudaEventDisableTiming);
        cudaEventCreateWithFlags(&evGate, cudaEventDisableTiming);
        cudaEventCreateWithFlags(&evD1,   cudaEventDisableTiming);
        cudaEventCreateWithFlags(&evD2,   cudaEventDisableTiming);
        cudaEventCreateWithFlags(&evD3,   cudaEventDisableTiming);
    }
};
}

extern "C" void kernel_launch(void* const* d_in, const int* in_sizes, int n_in,
                              void* d_out, int out_size) {
    const float* z      = (const float*)d_in[0];
    const float* Cells  = (const float*)d_in[1];
    const float* hidden = (const float*)d_in[2];
    const float* W_buf  = (const float*)d_in[3];
    const float* b_buf  = (const float*)d_in[4];
    const float* W_r1   = (const float*)d_in[5];
    const float* b_r1   = (const float*)d_in[6];
    const float* W_r2   = (const float*)d_in[7];
    const float* b_r2   = (const float*)d_in[8];
    const float* W_r3   = (const float*)d_in[9];
    const float* b_r3   = (const float*)d_in[10];
    const float* W_l1   = (const float*)d_in[11];
    const float* b_l1   = (const float*)d_in[12];
    const float* W_l2   = (const float*)d_in[13];
    const float* b_l2   = (const float*)d_in[14];
    const float* W_l3   = (const float*)d_in[15];
    const float* b_l3   = (const float*)d_in[16];
    const float* W_I    = (const float*)d_in[17];
    const float* b_I    = (const float*)d_in[18];
    const float* W_F    = (const float*)d_in[19];
    const float* b_F    = (const float*)d_in[20];
    const float* W_O    = (const float*)d_in[21];
    const float* b_O    = (const float*)d_in[22];
    const float* W_C    = (const float*)d_in[23];
    const float* b_C    = (const float*)d_in[24];
    const float* W_d    = (const float*)d_in[25];
    const float* b_d    = (const float*)d_in[26];

    float* out = (float*)d_out;

    __half *wt, *zb, *cellsH, *proj, *bl, *rA, *rB, *rC, *rD, *xh, *hnewH;
    float *biasG, *gpart, *gdec;
    cudaGetSymbolAddress((void**)&wt, h_wt);
    cudaGetSymbolAddress((void**)&zb, h_zb);
    cudaGetSymbolAddress((void**)&cellsH, h_cells);
    cudaGetSymbolAddress((void**)&proj, h_proj);
    cudaGetSymbolAddress((void**)&bl, h_bl);
    cudaGetSymbolAddress((void**)&rA, h_rA);
    cudaGetSymbolAddress((void**)&rB, h_rB);
    cudaGetSymbolAddress((void**)&rC, h_rC);
    cudaGetSymbolAddress((void**)&rD, h_rD);
    cudaGetSymbolAddress((void**)&xh, h_xh);
    cudaGetSymbolAddress((void**)&hnewH, h_hnew);
    cudaGetSymbolAddress((void**)&biasG, g_bias);
    cudaGetSymbolAddress((void**)&gpart, g_part);
    cudaGetSymbolAddress((void**)&gdec, g_dec);

    static StreamPool pool;
    cudaStream_t s1 = pool.s1, s2 = pool.s2, s3 = pool.s3;
    cudaStream_t m = 0;       // capturing (legacy) stream

    cudaEventRecord(pool.evFork, m);

    // ---- s1: gate weights (full-K transposes) + hidden-slice partial gate GEMM
    cudaStreamWaitEvent(s1, pool.evFork, 0);
    launch_wtrans<true>(s1, W_I, wt + OFF_G, GIN, U, 0);
    launch_wtrans<true>(s1, W_F, wt + OFF_G, GIN, U, 1);
    launch_wtrans<true>(s1, W_O, wt + OFF_G, GIN, U, 2);
    launch_wtrans<true>(s1, W_C, wt + OFF_G, GIN, U, 3);
    fuse_bias_perm_k<<<(NG + 255) / 256, 256, 0, s1>>>(b_I, b_F, b_O, b_C, biasG);
    copy_hidden_k<<<(ROWS * (U / 2) + 255) / 256, 256, 0, s1>>>(hidden, xh);
    // pass 1: gpart = xh[:, XDIM:] @ Wg[:, XDIM:]^T  (K = U)
    launch_hg<0, false, 8>(s1, xh + XDIM, GIN, wt + OFF_G + XDIM, GIN, nullptr,
                           gpart, NG, ROWS, NG, U);
    cudaEventRecord(pool.evS1, s1);

    // ---- s2: projection path (concurrent with main's buffer GEMM)
    cudaStreamWaitEvent(s2, pool.evFork, 0);
    launch_wtrans<false>(s2, W_r1,                 wt + OFF_R1A, U, H);
    launch_wtrans<false>(s2, W_r1 + (size_t)U * H, wt + OFF_R1B, U, H);
    launch_wtrans<false>(s2, W_l1,                 wt + OFF_L1A, U, H);
    round_copy_k<<<(ROWS * U + 255) / 256, 256, 0, s2>>>(Cells, cellsH, ROWS * U);
    launch_hg<0, true, 4>(s2, cellsH, U, wt + OFF_R1A, U, nullptr, proj, 1536, ROWS, 1536, U);
    cudaEventRecord(pool.evProj, s2);
    launch_wtrans<false>(s2, W_l2, wt + OFF_L2, H, H);
    launch_wtrans<false>(s2, W_l3, wt + OFF_L3, H, H);

    // ---- main: buffer path FIRST (critical for evBl), deferred small wtrans after
    transpose_z_k<<<(ROWS * DT + 255) / 256, 256, 0, m>>>(z, zb);
    launch_wtrans<false>(m, W_buf, wt + OFF_BUF, DT, BUF);
    launch_wtrans<false>(m, W_l1 + (size_t)U * H, wt + OFF_L1B, BUF, H);
    launch_hg<1, true, 4>(m, zb, DT, wt + OFF_BUF, DT, b_buf, xh, GIN, ROWS, BUF, DT);
    launch_hg<0, true, 4>(m, xh, GIN, wt + OFF_L1B, BUF, nullptr, bl, H, ROWS, H, BUF);
    cudaEventRecord(pool.evBl, m);
    launch_wtrans<false>(m, W_r2, wt + OFF_R2, H, H);
    launch_wtrans<false>(m, W_r3, wt + OFF_R3, H, H);
    launch_wtrans<false>(m, W_d, wt + OFF_D, U, Dd);

    // ---- s2: lambda path (combine -> rC, l2 -> rD, l3 -> rC)
    cudaStreamWaitEvent(s2, pool.evBl, 0);
    pair_combine_k<<<(PROWS * (H / 2) + 255) / 256, 256, 0, s2>>>(proj + 1024, 1536, bl, H, b_l1, rC);
    launch_hg<2, true, 8>(s2, rC, H, wt + OFF_L2, H, b_l2, rD, H, PROWS, H, H);
    launch_hg<2, true, 8>(s2, rD, H, wt + OFF_L3, H, b_l3, rC, H, PROWS, H, H);
    cudaEventRecord(pool.evS2, s2);

    // ---- main: rho path (combine -> rA, r2 -> rB, r3 -> rA)
    cudaStreamWaitEvent(m, pool.evProj, 0);
    pair_combine_k<<<(PROWS * (H / 2) + 255) / 256, 256, 0, m>>>(proj, 1536, proj + 512, 1536, b_r1, rA);
    launch_hg<2, true, 8>(m, rA, H, wt + OFF_R2, H, b_r2, rB, H, PROWS, H, H);
    launch_hg<2, true, 8>(m, rB, H, wt + OFF_R3, H, b_r3, rA, H, PROWS, H, H);

    // ---- join: reduce, then final gate pass (K = XDIM) with fused LSTM epilogue
    cudaStreamWaitEvent(m, pool.evS2, 0);
    reduce_inter_k<<<(ROWS * (H / 2) + 255) / 256, 256, 0, m>>>(rA, rC, xh);
    cudaStreamWaitEvent(m, pool.evS1, 0);
    launch_hg<5, false, 8>(m, xh, GIN, wt + OFF_G, GIN, biasG,
                           nullptr, 0, ROWS, NG, XDIM,
                           gpart, Cells, out + OUT_OFF_C, out + OUT_OFF_H, hnewH);
    cudaEventRecord(pool.evGate, m);

    // ---- decode: split-K x4 on 4 streams (NI=2 -> BN=64, exact fit)
    // slices: K offsets {0, 512, 1024, 1536}, lengths {512, 512, 512, 520}
    launch_hg<0, false, 2>(m, hnewH, U, wt + OFF_D, U, nullptr,
                           gdec + 0 * DSZ, Dd, ROWS, Dd, 512);
    cudaStreamWaitEvent(s1, pool.evGate, 0);
    launch_hg<0, false, 2>(s1, hnewH + 512, U, wt + OFF_D + 512, U, nullptr,
                           gdec + 1 * DSZ, Dd, ROWS, Dd, 512);
    cudaEventRecord(pool.evD1, s1);
    cudaStreamWaitEvent(s2, pool.evGate, 0);
    launch_hg<0, false, 2>(s2, hnewH + 1024, U, wt + OFF_D + 1024, U, nullptr,
                           gdec + 2 * DSZ, Dd, ROWS, Dd, 512);
    cudaEventRecord(pool.evD2, s2);
    cudaStreamWaitEvent(s3, pool.evGate, 0);
    launch_hg<0, false, 2>(s3, hnewH + 1536, U, wt + OFF_D + 1536, U, nullptr,
                           gdec + 3 * DSZ, Dd, ROWS, Dd, 520);
    cudaEventRecord(pool.evD3, s3);

    cudaStreamWaitEvent(m, pool.evD1, 0);
    cudaStreamWaitEvent(m, pool.evD2, 0);
    cudaStreamWaitEvent(m, pool.evD3, 0);
    decode_sum_k<<<(DSZ + 255) / 256, 256, 0, m>>>(gdec, b_d, out);
}

// round 15
// speedup vs baseline: 1.5429x; 1.0263x over previous
#include <cuda_runtime.h>
#include <cuda_fp16.h>
#include <math.h>
#include <stdint.h>

// ================= problem constants =================
namespace {
constexpr int Bb   = 256;
constexpr int Tt   = 15;
constexpr int Ns   = 8;
constexpr int Dd   = 64;
constexpr int U    = 2056;
constexpr int H    = 512;
constexpr int BUF  = 1680;
constexpr int XDIM = BUF + 2 * H;   // 2704
constexpr int GIN  = XDIM + U;      // 4760
constexpr int ROWS = Bb * Ns;       // 2048
constexpr int PROWS = ROWS * Ns;    // 16384
constexpr int DT   = Dd * Tt;       // 960
constexpr int NG   = 4 * U;         // 8224 fused (interleaved) gate width
constexpr int OUT_OFF_C   = ROWS * Dd;
constexpr int OUT_OFF_H   = OUT_OFF_C + ROWS * U;
constexpr int DSZ  = ROWS * Dd;     // decode partial slice size

// transposed-weight scratch offsets (halfs)
constexpr size_t OFF_BUF = 0;                                 // 1680 x 960
constexpr size_t OFF_R1A = OFF_BUF + (size_t)1680 * 960;      // 512 x 2056 (fused x3)
constexpr size_t OFF_R1B = OFF_R1A + (size_t)512 * 2056;
constexpr size_t OFF_L1A = OFF_R1B + (size_t)512 * 2056;
constexpr size_t OFF_L1B = OFF_L1A + (size_t)512 * 2056;      // 512 x 1680
constexpr size_t OFF_R2  = OFF_L1B + (size_t)512 * 1680;      // 512 x 512
constexpr size_t OFF_R3  = OFF_R2 + (size_t)512 * 512;
constexpr size_t OFF_L2  = OFF_R3 + (size_t)512 * 512;
constexpr size_t OFF_L3  = OFF_L2 + (size_t)512 * 512;
constexpr size_t OFF_G   = OFF_L3 + (size_t)512 * 512;        // 8224 x 4760 interleaved gates
constexpr size_t OFF_D   = OFF_G + (size_t)NG * 4760;         // 64 x 2056
constexpr size_t WT_TOTAL = OFF_D + (size_t)64 * 2056;
}

// ================= scratch (static device memory) =================
__device__ __half h_wt[WT_TOTAL];
__device__ __half h_zb[ROWS * DT];
__device__ __half h_cells[ROWS * U];
__device__ __half h_proj[ROWS * 1536];          // [ai | aj | al]
__device__ __half h_bl[ROWS * H];
__device__ __half h_rA[(size_t)PROWS * H];
__device__ __half h_rB[(size_t)PROWS * H];
__device__ __half h_rC[(size_t)PROWS * H];
__device__ __half h_rD[(size_t)PROWS * H];
__device__ __half h_xh[(size_t)ROWS * GIN];
__device__ __half h_hnew[ROWS * U];
__device__ float  g_part[(size_t)ROWS * NG];    // hidden-slice partial gate sums
__device__ float  g_dec[4 * DSZ];               // split-K decode partials
__device__ float  g_bias[NG];

// ================= helpers =================
__device__ __forceinline__ uint32_t smem_u32(const void* p) {
    uint32_t a;
    asm("{ .reg .u64 t; cvta.to.shared.u64 t, %1; cvt.u32.u64 %0, t; }" : "=r"(a) : "l"(p));
    return a;
}

#define CP_ASYNC(dst, src, sz) \
    asm volatile("cp.async.cg.shared.global [%0], [%1], 16, %2;" \
        :: "r"(dst), "l"(src), "r"(sz))
#define CP_COMMIT() asm volatile("cp.async.commit_group;" ::: "memory")
#define CP_WAIT(N)  asm volatile("cp.async.wait_group %0;" :: "n"(N) : "memory")

#define MMA_F16(d, a, b) \
    asm volatile("mma.sync.aligned.m16n8k16.row.col.f32.f16.f16.f32 " \
        "{%0,%1,%2,%3}, {%4,%5,%6,%7}, {%8,%9}, {%0,%1,%2,%3};" \
        : "+f"((d)[0]), "+f"((d)[1]), "+f"((d)[2]), "+f"((d)[3]) \
        : "r"((a)[0]), "r"((a)[1]), "r"((a)[2]), "r"((a)[3]), \
          "r"((b)[0]), "r"((b)[1]))

#define LDMATRIX_X4(r0, r1, r2, r3, addr) \
    asm volatile("ldmatrix.sync.aligned.m8n8.x4.shared.b16 {%0,%1,%2,%3}, [%4];" \
        : "=r"(r0), "=r"(r1), "=r"(r2), "=r"(r3) : "r"(addr))

// ================= activations =================
// ACT: 0 none, 1 elu, 2 gelu, 3 sigmoid, 4 tanh, 5 fused-gate epilogue (w/ partial)
__device__ __forceinline__ float act_apply(float x, int ACT) {
    if (ACT == 1) return x > 0.f ? x : expm1f(x);
    if (ACT == 2) return 0.5f * x * (1.f + erff(x * 0.70710678118654752440f));
    if (ACT == 3) return 1.f / (1.f + expf(-x));
    if (ACT == 4) return tanhf(x);
    return x;
}
__device__ __forceinline__ float sigmoidf_(float x) { return 1.f / (1.f + expf(-x)); }

// ================= fp16 mma GEMM (multi-stage cp.async + ldmatrix) =================
// C = act(A @ Wt^T + bias). A: (M,K) halfs stride lda. Wt: (Nd,K) halfs stride ldw.
// CTA tile 128 x (32*NI) x 64. 256 thr, 8 warps (2m x 4n), warp tile 64 x (8*NI).
// NI==8: 4-stage pipeline, 1 CTA/SM. NI<8: 3-stage, 2 CTAs/SM.
// ACT==5 (NI==8): interleaved-gate LSTM epilogue, adds `partial` before activation.
template <int ACT, bool HOUT, int NI>
__global__ void __launch_bounds__(256, (NI == 8) ? 1 : 2)
hgemm(const __half* __restrict__ A, int lda,
      const __half* __restrict__ Wt, int ldw,
      const float* __restrict__ bias,
      void* __restrict__ Cv, int ldc,
      int M, int Nd, int K,
      const float* __restrict__ partial,
      const float* __restrict__ cells,
      float* __restrict__ outC,
      float* __restrict__ outH,
      __half* __restrict__ outHh) {
    constexpr int BN = 32 * NI;
    constexpr int STG = (128 + BN) * 64 * 2;     // bytes per stage
    constexpr int STAGES = (NI == 8) ? 4 : 3;
    extern __shared__ __align__(16) char smraw[];

    const int tid = threadIdx.x;
    const int lane = tid & 31;
    const int wid = tid >> 5;
    const int g = lane >> 2, t = lane & 3;
    const int wm = wid >> 2, wn = wid & 3;
    const int bm = blockIdx.y * 128, bn = blockIdx.x * BN;

    float acc[4][NI][4];
#pragma unroll
    for (int i = 0; i < 4; i++)
#pragma unroll
        for (int j = 0; j < NI; j++)
#pragma unroll
            for (int q = 0; q < 4; q++) acc[i][j][q] = 0.f;

    const int nt = (K + 63) / 64;

    auto load_tile = [&](int kt, int s) {
        __half* As = (__half*)(smraw + s * STG);
        __half* Bs = As + 8192;
        const int k0 = kt * 64;
#pragma unroll
        for (int i = 0; i < 4; i++) {
            int idx = tid + i * 256;
            int row = idx >> 3, c8 = idx & 7;
            int kk = k0 + c8 * 8;
            uint32_t dst = smem_u32(As + row * 64 + ((c8 ^ (row & 7)) << 3));
            const __half* src = A + (size_t)(bm + row) * lda + kk;
            int sz = (kk < K) ? 16 : 0;
            CP_ASYNC(dst, src, sz);
        }
#pragma unroll
        for (int i = 0; i < NI; i++) {
            int idx = tid + i * 256;
            int row = idx >> 3, c8 = idx & 7;
            int kk = k0 + c8 * 8;
            int n = bn + row;
            int nc = (n < Nd) ? n : (Nd - 1);
            uint32_t dst = smem_u32(Bs + row * 64 + ((c8 ^ (row & 7)) << 3));
            const __half* src = Wt + (size_t)nc * ldw + kk;
            int sz = (n < Nd && kk < K) ? 16 : 0;
            CP_ASYNC(dst, src, sz);
        }
    };

    // ldmatrix lane decomposition
    const int lm = lane >> 3, lr = lane & 7;

    auto compute_tile = [&](int s) {
        const uint32_t sbase = smem_u32(smraw + s * STG);
        const uint32_t a_base = sbase + (uint32_t)(wm * 64 + (lm & 1) * 8 + lr) * 128;
        const int ad = lm >> 1;
        const uint32_t b_base = sbase + 16384u + (uint32_t)(wn * (8 * NI) + (lm >> 1) * 8 + lr) * 128;
        const int bd = lm & 1;
#pragma unroll
        for (int ks = 0; ks < 4; ks++) {
            uint32_t a[4][4], b[NI][2];
#pragma unroll
            for (int mi = 0; mi < 4; mi++) {
                uint32_t addr = a_base + (uint32_t)(mi * 16 * 128) + ((uint32_t)((2 * ks + ad) ^ lr) << 4);
                LDMATRIX_X4(a[mi][0], a[mi][1], a[mi][2], a[mi][3], addr);
            }
#pragma unroll
            for (int np = 0; np < NI / 2; np++) {
                uint32_t addr = b_base + (uint32_t)(np * 16 * 128) + ((uint32_t)((2 * ks + bd) ^ lr) << 4);
                LDMATRIX_X4(b[2 * np][0], b[2 * np][1], b[2 * np + 1][0], b[2 * np + 1][1], addr);
            }
#pragma unroll
            for (int mi = 0; mi < 4; mi++)
#pragma unroll
                for (int ni = 0; ni < NI; ni++)
                    MMA_F16(acc[mi][ni], a[mi], b[ni]);
        }
    };

    // STAGES-deep pipeline, one __syncthreads per K-tile.
    {
        int pre = (nt < STAGES - 1) ? nt : (STAGES - 1);
        for (int i = 0; i < pre; i++) { load_tile(i, i); CP_COMMIT(); }
    }
    int sc = 0;
    for (int kt = 0; kt < nt; kt++) {
        if (STAGES == 4) {
            if (kt < nt - 2)       { CP_WAIT(2); }
            else if (kt == nt - 2) { CP_WAIT(1); }
            else                   { CP_WAIT(0); }
        } else {
            if (kt < nt - 1)       { CP_WAIT(1); }
            else                   { CP_WAIT(0); }
        }
        __syncthreads();
        compute_tile(sc);
        if (kt + STAGES - 1 < nt) {
            int sl = sc + (STAGES - 1); if (sl >= STAGES) sl -= STAGES;
            load_tile(kt + STAGES - 1, sl);
            CP_COMMIT();
        }
        if (++sc == STAGES) sc = 0;
    }

    if (ACT == 5) {
        // fused LSTM-gate epilogue (NI == 8, interleaved layout) + partial add
#pragma unroll
        for (int blk = 0; blk < 2; blk++) {
            const int base = bn + wn * 64 + blk * 32;
            if (base >= Nd) continue;
            const int ub = base >> 5;
            const int u = ub * 8 + 2 * t;
            const int colI = base + 2 * t;
            const float bI0 = bias[colI],      bI1 = bias[colI + 1];
            const float bF0 = bias[colI + 8],  bF1 = bias[colI + 9];
            const float bO0 = bias[colI + 16], bO1 = bias[colI + 17];
            const float bC0 = bias[colI + 24], bC1 = bias[colI + 25];
#pragma unroll
            for (int mi = 0; mi < 4; mi++) {
                const int r0 = bm + wm * 64 + mi * 16 + g;
#pragma unroll
                for (int half_ = 0; half_ < 2; half_++) {
                    const int r = r0 + half_ * 8;
                    const int e0 = half_ * 2, e1 = half_ * 2 + 1;
                    const float* prow = partial + (size_t)r * NG + colI;
                    float2 pI = *(const float2*)(prow);
                    float2 pF = *(const float2*)(prow + 8);
                    float2 pO = *(const float2*)(prow + 16);
                    float2 pC = *(const float2*)(prow + 24);
                    float I0 = sigmoidf_(acc[mi][blk * 4 + 0][e0] + pI.x + bI0);
                    float I1 = sigmoidf_(acc[mi][blk * 4 + 0][e1] + pI.y + bI1);
                    float F0 = sigmoidf_(acc[mi][blk * 4 + 1][e0] + pF.x + bF0);
                    float F1 = sigmoidf_(acc[mi][blk * 4 + 1][e1] + pF.y + bF1);
                    float O0 = sigmoidf_(acc[mi][blk * 4 + 2][e0] + pO.x + bO0);
                    float O1 = sigmoidf_(acc[mi][blk * 4 + 2][e1] + pO.y + bO1);
                    float T0 = tanhf(acc[mi][blk * 4 + 3][e0] + pC.x + bC0);
                    float T1 = tanhf(acc[mi][blk * 4 + 3][e1] + pC.y + bC1);
                    float2 cv = *(const float2*)(cells + (size_t)r * U + u);
                    float c0 = F0 * cv.x + I0 * T0;
                    float c1 = F1 * cv.y + I1 * T1;
                    float hh0 = O0 * tanhf(c0);
                    float hh1 = O1 * tanhf(c1);
                    *(float2*)(outC + (size_t)r * U + u) = make_float2(c0, c1);
                    *(float2*)(outH + (size_t)r * U + u) = make_float2(hh0, hh1);
                    *(__half2*)(outHh + (size_t)r * U + u) = __floats2half2_rn(hh0, hh1);
                }
            }
        }
        return;
    }

#pragma unroll
    for (int ni = 0; ni < NI; ni++) {
        const int col0 = bn + wn * (8 * NI) + ni * 8 + 2 * t;
        if (col0 >= Nd) continue;
        const float b0 = bias ? bias[col0] : 0.f;
        const float b1 = bias ? bias[col0 + 1] : 0.f;
#pragma unroll
        for (int mi = 0; mi < 4; mi++) {
            const int r0 = bm + wm * 64 + mi * 16 + g;
            float v0 = act_apply(acc[mi][ni][0] + b0, ACT);
            float v1 = act_apply(acc[mi][ni][1] + b1, ACT);
            float v2 = act_apply(acc[mi][ni][2] + b0, ACT);
            float v3 = act_apply(acc[mi][ni][3] + b1, ACT);
            if (HOUT) {
                __half* C = (__half*)Cv;
                *(__half2*)(C + (size_t)r0 * ldc + col0)       = __floats2half2_rn(v0, v1);
                *(__half2*)(C + (size_t)(r0 + 8) * ldc + col0) = __floats2half2_rn(v2, v3);
            } else {
                float* C = (float*)Cv;
                *(float2*)(C + (size_t)r0 * ldc + col0)       = make_float2(v0, v1);
                *(float2*)(C + (size_t)(r0 + 8) * ldc + col0) = make_float2(v2, v3);
            }
        }
    }
}

// ================= fast weight transpose + fp16 =================
// W (K,N) f32 -> Wt (N,K) f16. 64x64 tiles, float4 loads, 16B stores.
// PERM: output row = (n>>3)*32 + gate*8 + (n&7)
template <bool PERM>
__global__ void wtrans_k(const float* __restrict__ W, __half* __restrict__ Wt,
                         int K, int N, int gate) {
    __shared__ float ts[64][65];
    const int kb = blockIdx.y * 64, nb = blockIdx.x * 64;
    const int tid = threadIdx.x;
#pragma unroll
    for (int i = 0; i < 4; i++) {
        int idx = tid + i * 256;
        int k = idx >> 4, q = idx & 15;
        int gk = kb + k, gn = nb + q * 4;
        float4 v = make_float4(0.f, 0.f, 0.f, 0.f);
        if (gk < K && gn < N) v = *(const float4*)(W + (size_t)gk * N + gn);
        ts[k][q * 4 + 0] = v.x;
        ts[k][q * 4 + 1] = v.y;
        ts[k][q * 4 + 2] = v.z;
        ts[k][q * 4 + 3] = v.w;
    }
    __syncthreads();
#pragma unroll
    for (int i = 0; i < 2; i++) {
        int idx = tid + i * 256;
        int n = idx >> 3, c = idx & 7;
        int gn = nb + n;
        int gk = kb + c * 8;
        if (gn >= N || gk >= K) continue;
        __half hv[8];
#pragma unroll
        for (int j = 0; j < 8; j++) hv[j] = __float2half_rn(ts[c * 8 + j][n]);
        int row = PERM ? (((gn >> 3) << 5) + gate * 8 + (gn & 7)) : gn;
        *(uint4*)(Wt + (size_t)row * K + gk) = *(uint4*)hv;
    }
}

// ================= pointwise kernels =================
__global__ void transpose_z_k(const float* __restrict__ z, __half* __restrict__ zb) {
    int idx = blockIdx.x * blockDim.x + threadIdx.x;
    if (idx >= ROWS * DT) return;
    int bn = idx / DT;
    int rem = idx - bn * DT;
    int d = rem / Tt;
    int t = rem - d * Tt;
    int b = bn >> 3;
    int n = bn & 7;
    zb[idx] = __float2half_rn(z[((size_t)(b * Tt + t) * Ns + n) * Dd + d]);
}

__global__ void round_copy_k(const float* __restrict__ src, __half* __restrict__ dst, int n) {
    int idx = blockIdx.x * blockDim.x + threadIdx.x;
    if (idx >= n) return;
    dst[idx] = __float2half_rn(src[idx]);
}

__global__ void fuse_bias_perm_k(const float* __restrict__ bI, const float* __restrict__ bF,
                                 const float* __restrict__ bO, const float* __restrict__ bC,
                                 float* __restrict__ dst) {
    int idx = blockIdx.x * blockDim.x + threadIdx.x;
    if (idx >= NG) return;
    int gate = idx / U, u = idx - gate * U;
    const float* src = (gate == 0) ? bI : (gate == 1) ? bF : (gate == 2) ? bO : bC;
    dst[((u >> 3) << 5) + gate * 8 + (u & 7)] = src[u];
}

__global__ void pair_combine_k(const __half* __restrict__ ai, int ldi,
                               const __half* __restrict__ aj, int ldj,
                               const float* __restrict__ bias, __half* __restrict__ out) {
    int idx = blockIdx.x * blockDim.x + threadIdx.x;   // over PROWS * (H/2)
    if (idx >= PROWS * (H / 2)) return;
    int row = idx / (H / 2);
    int h2 = idx - row * (H / 2);
    int j = row & 7;
    int i_row = row >> 3;
    int b = i_row >> 3;
    int j_row = (b << 3) + j;

    float2 a = __half22float2(*((const __half2*)(ai + (size_t)i_row * ldi) + h2));
    float2 c = __half22float2(*((const __half2*)(aj + (size_t)j_row * ldj) + h2));
    float2 bb = ((const float2*)bias)[h2];
    float o0 = act_apply(a.x + c.x + bb.x, 2);
    float o1 = act_apply(a.y + c.y + bb.y, 2);
    ((__half2*)(out + (size_t)row * H))[h2] = __floats2half2_rn(o0, o1);
}

__global__ void reduce_inter_k(const __half* __restrict__ rA, const __half* __restrict__ rB,
                               __half* __restrict__ xh) {
    int idx = blockIdx.x * blockDim.x + threadIdx.x;   // over ROWS * (H/2)
    if (idx >= ROWS * (H / 2)) return;
    int row = idx / (H / 2);
    int h2 = idx - row * (H / 2);
    float s0 = 0.f, s1 = 0.f, m0 = -INFINITY, m1 = -INFINITY;
#pragma unroll
    for (int j = 0; j < Ns; j++) {
        size_t p = (size_t)(row * Ns + j) * (H / 2) + h2;
        float2 va = __half22float2(((const __half2*)rA)[p]);
        float2 vb = __half22float2(((const __half2*)rB)[p]);
        float v0 = va.x + vb.x, v1 = va.y + vb.y;
        s0 += v0; s1 += v1;
        m0 = fmaxf(m0, v0); m1 = fmaxf(m1, v1);
    }
    __half* base = xh + (size_t)row * GIN;
    *(__half2*)(base + BUF + 2 * h2)     = __floats2half2_rn(s0, s1);
    *(__half2*)(base + BUF + H + 2 * h2) = __floats2half2_rn(m0, m1);
}

__global__ void copy_hidden_k(const float* __restrict__ hidden, __half* __restrict__ xh) {
    int idx = blockIdx.x * blockDim.x + threadIdx.x;   // over ROWS * (U/2)
    if (idx >= ROWS * (U / 2)) return;
    int row = idx / (U / 2);
    int c2 = idx - row * (U / 2);
    float2 v = ((const float2*)(hidden + (size_t)row * U))[c2];
    *(__half2*)(xh + (size_t)row * GIN + XDIM + 2 * c2) = __floats2half2_rn(v.x, v.y);
}

__global__ void decode_sum_k(const float* __restrict__ p, const float* __restrict__ bias,
                             float* __restrict__ out) {
    int idx = blockIdx.x * blockDim.x + threadIdx.x;   // over DSZ
    if (idx >= DSZ) return;
    int col = idx & (Dd - 1);
    out[idx] = ((p[idx] + p[DSZ + idx]) + (p[2 * DSZ + idx] + p[3 * DSZ + idx])) + bias[col];
}

// ================= host =================
template <int ACT, bool HOUT, int NI>
static void launch_hg(cudaStream_t st,
                      const __half* A, int lda, const __half* Wt, int ldw,
                      const float* bias,
                      void* C, int ldc, int M, int Nd, int K,
                      const float* partial = nullptr,
                      const float* cells = nullptr, float* outC = nullptr,
                      float* outH = nullptr, __half* outHh = nullptr) {
    constexpr int BN = 32 * NI;
    constexpr int STAGES = (NI == 8) ? 4 : 3;
    constexpr int smem = STAGES * ((128 + BN) * 64 * 2);
    cudaFuncSetAttribute(hgemm<ACT, HOUT, NI>, cudaFuncAttributeMaxDynamicSharedMemorySize, smem);
    dim3 grid((Nd + BN - 1) / BN, M / 128);
    hgemm<ACT, HOUT, NI><<<grid, 256, smem, st>>>(A, lda, Wt, ldw, bias, C, ldc, M, Nd, K,
                                                  partial, cells, outC, outH, outHh);
}

template <bool PERM>
static void launch_wtrans(cudaStream_t st, const float* W, __half* Wt, int K, int N, int gate = 0) {
    dim3 grid((N + 63) / 64, (K + 63) / 64);
    wtrans_k<PERM><<<grid, 256, 0, st>>>(W, Wt, K, N, gate);
}

// Persistent stream/event pool (created once on the pre-baseline correctness
// run; reused by every captured call; never destroyed).
namespace {
struct StreamPool {
    cudaStream_t s1, s2, s3;
    cudaEvent_t evFork, evS1, evProj, evBl, evS2, evGate, evD1, evD2, evD3;
    StreamPool() {
        cudaStreamCreateWithFlags(&s1, cudaStreamNonBlocking);
        cudaStreamCreateWithFlags(&s2, cudaStreamNonBlocking);
        cudaStreamCreateWithFlags(&s3, cudaStreamNonBlocking);
        cudaEventCreateWithFlags(&evFork, cudaEventDisableTiming);
        cudaEventCreateWithFlags(&evS1,   cudaEventDisableTiming);
        cudaEventCreateWithFlags(&evProj, cudaEventDisableTiming);
        cudaEventCreateWithFlags(&evBl,   cudaEventDisableTiming);
        cudaEventCreateWithFlags(&evS2,   cudaEventDisableTiming);
        cudaEventCreateWithFlags(&evGate, cudaEventDisableTiming);
        cudaEventCreateWithFlags(&evD1,   cudaEventDisableTiming);
        cudaEventCreateWithFlags(&evD2,   cudaEventDisableTiming);
        cudaEventCreateWithFlags(&evD3,   cudaEventDisableTiming);
    }
};
}

extern "C" void kernel_launch(void* const* d_in, const int* in_sizes, int n_in,
                              void* d_out, int out_size) {
    const float* z      = (const float*)d_in[0];
    const float* Cells  = (const float*)d_in[1];
    const float* hidden = (const float*)d_in[2];
    const float* W_buf  = (const float*)d_in[3];
    const float* b_buf  = (const float*)d_in[4];
    const float* W_r1   = (const float*)d_in[5];
    const float* b_r1   = (const float*)d_in[6];
    const float* W_r2   = (const float*)d_in[7];
    const float* b_r2   = (const float*)d_in[8];
    const float* W_r3   = (const float*)d_in[9];
    const float* b_r3   = (const float*)d_in[10];
    const float* W_l1   = (const float*)d_in[11];
    const float* b_l1   = (const float*)d_in[12];
    const float* W_l2   = (const float*)d_in[13];
    const float* b_l2   = (const float*)d_in[14];
    const float* W_l3   = (const float*)d_in[15];
    const float* b_l3   = (const float*)d_in[16];
    const float* W_I    = (const float*)d_in[17];
    const float* b_I    = (const float*)d_in[18];
    const float* W_F    = (const float*)d_in[19];
    const float* b_F    = (const float*)d_in[20];
    const float* W_O    = (const float*)d_in[21];
    const float* b_O    = (const float*)d_in[22];
    const float* W_C    = (const float*)d_in[23];
    const float* b_C    = (const float*)d_in[24];
    const float* W_d    = (const float*)d_in[25];
    const float* b_d    = (const float*)d_in[26];

    float* out = (float*)d_out;

    __half *wt, *zb, *cellsH, *proj, *bl, *rA, *rB, *rC, *rD, *xh, *hnewH;
    float *biasG, *gpart, *gdec;
    cudaGetSymbolAddress((void**)&wt, h_wt);
    cudaGetSymbolAddress((void**)&zb, h_zb);
    cudaGetSymbolAddress((void**)&cellsH, h_cells);
    cudaGetSymbolAddress((void**)&proj, h_proj);
    cudaGetSymbolAddress((void**)&bl, h_bl);
    cudaGetSymbolAddress((void**)&rA, h_rA);
    cudaGetSymbolAddress((void**)&rB, h_rB);
    cudaGetSymbolAddress((void**)&rC, h_rC);
    cudaGetSymbolAddress((void**)&rD, h_rD);
    cudaGetSymbolAddress((void**)&xh, h_xh);
    cudaGetSymbolAddress((void**)&hnewH, h_hnew);
    cudaGetSymbolAddress((void**)&biasG, g_bias);
    cudaGetSymbolAddress((void**)&gpart, g_part);
    cudaGetSymbolAddress((void**)&gdec, g_dec);

    static StreamPool pool;
    cudaStream_t s1 = pool.s1, s2 = pool.s2, s3 = pool.s3;
    cudaStream_t m = 0;       // capturing (legacy) stream

    cudaEventRecord(pool.evFork, m);

    // ---- s1: gate weights (full-K transposes) + hidden-slice partial gate GEMM
    cudaStreamWaitEvent(s1, pool.evFork, 0);
    launch_wtrans<true>(s1, W_I, wt + OFF_G, GIN, U, 0);
    launch_wtrans<true>(s1, W_F, wt + OFF_G, GIN, U, 1);
    launch_wtrans<true>(s1, W_O, wt + OFF_G, GIN, U, 2);
    launch_wtrans<true>(s1, W_C, wt + OFF_G, GIN, U, 3);
    fuse_bias_perm_k<<<(NG + 255) / 256, 256, 0, s1>>>(b_I, b_F, b_O, b_C, biasG);
    copy_hidden_k<<<(ROWS * (U / 2) + 255) / 256, 256, 0, s1>>>(hidden, xh);
    // pass 1: gpart = xh[:, XDIM:] @ Wg[:, XDIM:]^T  (K = U)
    launch_hg<0, false, 8>(s1, xh + XDIM, GIN, wt + OFF_G + XDIM, GIN, nullptr,
                           gpart, NG, ROWS, NG, U);
    cudaEventRecord(pool.evS1, s1);

    // ---- s2: projection path (concurrent with main's buffer GEMM)
    cudaStreamWaitEvent(s2, pool.evFork, 0);
    launch_wtrans<false>(s2, W_r1,                 wt + OFF_R1A, U, H);
    launch_wtrans<false>(s2, W_r1 + (size_t)U * H, wt + OFF_R1B, U, H);
    launch_wtrans<false>(s2, W_l1,                 wt + OFF_L1A, U, H);
    round_copy_k<<<(ROWS * U + 255) / 256, 256, 0, s2>>>(Cells, cellsH, ROWS * U);
    launch_hg<0, true, 4>(s2, cellsH, U, wt + OFF_R1A, U, nullptr, proj, 1536, ROWS, 1536, U);
    cudaEventRecord(pool.evProj, s2);
    launch_wtrans<false>(s2, W_l2, wt + OFF_L2, H, H);
    launch_wtrans<false>(s2, W_l3, wt + OFF_L3, H, H);

    // ---- main: buffer path FIRST (critical for evBl), deferred small wtrans after
    transpose_z_k<<<(ROWS * DT + 255) / 256, 256, 0, m>>>(z, zb);
    launch_wtrans<false>(m, W_buf, wt + OFF_BUF, DT, BUF);
    launch_wtrans<false>(m, W_l1 + (size_t)U * H, wt + OFF_L1B, BUF, H);
    launch_hg<1, true, 4>(m, zb, DT, wt + OFF_BUF, DT, b_buf, xh, GIN, ROWS, BUF, DT);
    launch_hg<0, true, 4>(m, xh, GIN, wt + OFF_L1B, BUF, nullptr, bl, H, ROWS, H, BUF);
    cudaEventRecord(pool.evBl, m);
    launch_wtrans<false>(m, W_r2, wt + OFF_R2, H, H);
    launch_wtrans<false>(m, W_r3, wt + OFF_R3, H, H);
    launch_wtrans<false>(m, W_d, wt + OFF_D, U, Dd);

    // ---- s2: lambda path (combine -> rC, l2 -> rD, l3 -> rC), 2-CTA/SM NI=4 GEMMs
    cudaStreamWaitEvent(s2, pool.evBl, 0);
    pair_combine_k<<<(PROWS * (H / 2) + 255) / 256, 256, 0, s2>>>(proj + 1024, 1536, bl, H, b_l1, rC);
    launch_hg<2, true, 4>(s2, rC, H, wt + OFF_L2, H, b_l2, rD, H, PROWS, H, H);
    launch_hg<2, true, 4>(s2, rD, H, wt + OFF_L3, H, b_l3, rC, H, PROWS, H, H);
    cudaEventRecord(pool.evS2, s2);

    // ---- main: rho path (combine -> rA, r2 -> rB, r3 -> rA)
    cudaStreamWaitEvent(m, pool.evProj, 0);
    pair_combine_k<<<(PROWS * (H / 2) + 255) / 256, 256, 0, m>>>(proj, 1536, proj + 512, 1536, b_r1, rA);
    launch_hg<2, true, 4>(m, rA, H, wt + OFF_R2, H, b_r2, rB, H, PROWS, H, H);
    launch_hg<2, true, 4>(m, rB, H, wt + OFF_R3, H, b_r3, rA, H, PROWS, H, H);

    // ---- join: reduce, then final gate pass (K = XDIM) with fused LSTM epilogue
    cudaStreamWaitEvent(m, pool.evS2, 0);
    reduce_inter_k<<<(ROWS * (H / 2) + 255) / 256, 256, 0, m>>>(rA, rC, xh);
    cudaStreamWaitEvent(m, pool.evS1, 0);
    launch_hg<5, false, 8>(m, xh, GIN, wt + OFF_G, GIN, biasG,
                           nullptr, 0, ROWS, NG, XDIM,
                           gpart, Cells, out + OUT_OFF_C, out + OUT_OFF_H, hnewH);
    cudaEventRecord(pool.evGate, m);

    // ---- decode: split-K x4 on 4 streams (NI=2 -> BN=64, exact fit)
    launch_hg<0, false, 2>(m, hnewH, U, wt + OFF_D, U, nullptr,
                           gdec + 0 * DSZ, Dd, ROWS, Dd, 512);
    cudaStreamWaitEvent(s1, pool.evGate, 0);
    launch_hg<0, false, 2>(s1, hnewH + 512, U, wt + OFF_D + 512, U, nullptr,
                           gdec + 1 * DSZ, Dd, ROWS, Dd, 512);
    cudaEventRecord(pool.evD1, s1);
    cudaStreamWaitEvent(s2, pool.evGate, 0);
    launch_hg<0, false, 2>(s2, hnewH + 1024, U, wt + OFF_D + 1024, U, nullptr,
                           gdec + 2 * DSZ, Dd, ROWS, Dd, 512);
    cudaEventRecord(pool.evD2, s2);
    cudaStreamWaitEvent(s3, pool.evGate, 0);
    launch_hg<0, false, 2>(s3, hnewH + 1536, U, wt + OFF_D + 1536, U, nullptr,
                           gdec + 3 * DSZ, Dd, ROWS, Dd, 520);
    cudaEventRecord(pool.evD3, s3);

    cudaStreamWaitEvent(m, pool.evD1, 0);
    cudaStreamWaitEvent(m, pool.evD2, 0);
    cudaStreamWaitEvent(m, pool.evD3, 0);
    decode_sum_k<<<(DSZ + 255) / 256, 256, 0, m>>>(gdec, b_d, out);
}

// round 16
// speedup vs baseline: 1.8704x; 1.2123x over previous
#include <cuda_runtime.h>
#include <cuda_fp16.h>
#include <math.h>
#include <stdint.h>

// ================= problem constants =================
namespace {
constexpr int Bb   = 256;
constexpr int Tt   = 15;
constexpr int Ns   = 8;
constexpr int Dd   = 64;
constexpr int U    = 2056;
constexpr int H    = 512;
constexpr int BUF  = 1680;
constexpr int XDIM = BUF + 2 * H;   // 2704
constexpr int GIN  = XDIM + U;      // 4760
constexpr int ROWS = Bb * Ns;       // 2048
constexpr int PROWS = ROWS * Ns;    // 16384
constexpr int DT   = Dd * Tt;       // 960
constexpr int NG   = 4 * U;         // 8224 fused (interleaved) gate width
constexpr int OUT_OFF_C   = ROWS * Dd;
constexpr int OUT_OFF_H   = OUT_OFF_C + ROWS * U;
constexpr int DSZ  = ROWS * Dd;     // decode partial slice size

// transposed-weight scratch offsets (halfs)
constexpr size_t OFF_BUF = 0;                                 // 1680 x 960
constexpr size_t OFF_R1A = OFF_BUF + (size_t)1680 * 960;      // 512 x 2056 (fused x3)
constexpr size_t OFF_R1B = OFF_R1A + (size_t)512 * 2056;
constexpr size_t OFF_L1A = OFF_R1B + (size_t)512 * 2056;
constexpr size_t OFF_L1B = OFF_L1A + (size_t)512 * 2056;      // 512 x 1680
constexpr size_t OFF_R2  = OFF_L1B + (size_t)512 * 1680;      // 512 x 512
constexpr size_t OFF_R3  = OFF_R2 + (size_t)512 * 512;
constexpr size_t OFF_L2  = OFF_R3 + (size_t)512 * 512;
constexpr size_t OFF_L3  = OFF_L2 + (size_t)512 * 512;
constexpr size_t OFF_G   = OFF_L3 + (size_t)512 * 512;        // 8224 x 4760 interleaved gates
constexpr size_t OFF_D   = OFF_G + (size_t)NG * 4760;         // 64 x 2056
constexpr size_t WT_TOTAL = OFF_D + (size_t)64 * 2056;
}

// ================= scratch (static device memory) =================
__device__ __half h_wt[WT_TOTAL];
__device__ __half h_zb[ROWS * DT];
__device__ __half h_cells[ROWS * U];
__device__ __half h_proj[ROWS * 1536];          // [ai | aj | al]
__device__ __half h_bl[ROWS * H];
__device__ __half h_rA[(size_t)PROWS * H];
__device__ __half h_rB[(size_t)PROWS * H];
__device__ __half h_rC[(size_t)PROWS * H];
__device__ __half h_rD[(size_t)PROWS * H];
__device__ __half h_xh[(size_t)ROWS * GIN];
__device__ __half h_hnew[ROWS * U];
__device__ float  g_part[(size_t)ROWS * NG];    // hidden-slice partial gate sums
__device__ float  g_dec[4 * DSZ];               // split-K decode partials
__device__ float  g_bias[NG];

// ================= helpers =================
__device__ __forceinline__ uint32_t smem_u32(const void* p) {
    uint32_t a;
    asm("{ .reg .u64 t; cvta.to.shared.u64 t, %1; cvt.u32.u64 %0, t; }" : "=r"(a) : "l"(p));
    return a;
}

#define CP_ASYNC(dst, src, sz) \
    asm volatile("cp.async.cg.shared.global [%0], [%1], 16, %2;" \
        :: "r"(dst), "l"(src), "r"(sz))
#define CP_COMMIT() asm volatile("cp.async.commit_group;" ::: "memory")
#define CP_WAIT(N)  asm volatile("cp.async.wait_group %0;" :: "n"(N) : "memory")

#define MMA_F16(d, a, b) \
    asm volatile("mma.sync.aligned.m16n8k16.row.col.f32.f16.f16.f32 " \
        "{%0,%1,%2,%3}, {%4,%5,%6,%7}, {%8,%9}, {%0,%1,%2,%3};" \
        : "+f"((d)[0]), "+f"((d)[1]), "+f"((d)[2]), "+f"((d)[3]) \
        : "r"((a)[0]), "r"((a)[1]), "r"((a)[2]), "r"((a)[3]), \
          "r"((b)[0]), "r"((b)[1]))

#define LDMATRIX_X4(r0, r1, r2, r3, addr) \
    asm volatile("ldmatrix.sync.aligned.m8n8.x4.shared.b16 {%0,%1,%2,%3}, [%4];" \
        : "=r"(r0), "=r"(r1), "=r"(r2), "=r"(r3) : "r"(addr))

// ================= activations =================
// ACT: 0 none, 1 elu, 2 gelu, 3 sigmoid, 4 tanh, 5 fused-gate epilogue (w/ partial)
__device__ __forceinline__ float act_apply(float x, int ACT) {
    if (ACT == 1) return x > 0.f ? x : expm1f(x);
    if (ACT == 2) return 0.5f * x * (1.f + erff(x * 0.70710678118654752440f));
    if (ACT == 3) return 1.f / (1.f + expf(-x));
    if (ACT == 4) return tanhf(x);
    return x;
}
__device__ __forceinline__ float sigmoidf_(float x) { return 1.f / (1.f + expf(-x)); }

// ================= fp16 mma GEMM (multi-stage cp.async + ldmatrix) =================
// C = act(A @ Wt^T + bias). A: (M,K) halfs stride lda. Wt: (Nd,K) halfs stride ldw.
// CTA tile 128 x (32*NI) x 64. 256 thr, 8 warps (2m x 4n), warp tile 64 x (8*NI).
// NI==8: 4-stage pipeline, 1 CTA/SM. NI<8: 3-stage, 2 CTAs/SM.
// ACT==5 (NI==4 or 8): interleaved-gate LSTM epilogue, adds `partial`.
template <int ACT, bool HOUT, int NI>
__global__ void __launch_bounds__(256, (NI == 8) ? 1 : 2)
hgemm(const __half* __restrict__ A, int lda,
      const __half* __restrict__ Wt, int ldw,
      const float* __restrict__ bias,
      void* __restrict__ Cv, int ldc,
      int M, int Nd, int K,
      const float* __restrict__ partial,
      const float* __restrict__ cells,
      float* __restrict__ outC,
      float* __restrict__ outH,
      __half* __restrict__ outHh) {
    constexpr int BN = 32 * NI;
    constexpr int STG = (128 + BN) * 64 * 2;     // bytes per stage
    constexpr int STAGES = (NI == 8) ? 4 : 3;
    extern __shared__ __align__(16) char smraw[];

    const int tid = threadIdx.x;
    const int lane = tid & 31;
    const int wid = tid >> 5;
    const int g = lane >> 2, t = lane & 3;
    const int wm = wid >> 2, wn = wid & 3;
    const int bm = blockIdx.y * 128, bn = blockIdx.x * BN;

    float acc[4][NI][4];
#pragma unroll
    for (int i = 0; i < 4; i++)
#pragma unroll
        for (int j = 0; j < NI; j++)
#pragma unroll
            for (int q = 0; q < 4; q++) acc[i][j][q] = 0.f;

    const int nt = (K + 63) / 64;

    auto load_tile = [&](int kt, int s) {
        __half* As = (__half*)(smraw + s * STG);
        __half* Bs = As + 8192;
        const int k0 = kt * 64;
#pragma unroll
        for (int i = 0; i < 4; i++) {
            int idx = tid + i * 256;
            int row = idx >> 3, c8 = idx & 7;
            int kk = k0 + c8 * 8;
            uint32_t dst = smem_u32(As + row * 64 + ((c8 ^ (row & 7)) << 3));
            const __half* src = A + (size_t)(bm + row) * lda + kk;
            int sz = (kk < K) ? 16 : 0;
            CP_ASYNC(dst, src, sz);
        }
#pragma unroll
        for (int i = 0; i < NI; i++) {
            int idx = tid + i * 256;
            int row = idx >> 3, c8 = idx & 7;
            int kk = k0 + c8 * 8;
            int n = bn + row;
            int nc = (n < Nd) ? n : (Nd - 1);
            uint32_t dst = smem_u32(Bs + row * 64 + ((c8 ^ (row & 7)) << 3));
            const __half* src = Wt + (size_t)nc * ldw + kk;
            int sz = (n < Nd && kk < K) ? 16 : 0;
            CP_ASYNC(dst, src, sz);
        }
    };

    // ldmatrix lane decomposition
    const int lm = lane >> 3, lr = lane & 7;

    auto compute_tile = [&](int s) {
        const uint32_t sbase = smem_u32(smraw + s * STG);
        const uint32_t a_base = sbase + (uint32_t)(wm * 64 + (lm & 1) * 8 + lr) * 128;
        const int ad = lm >> 1;
        const uint32_t b_base = sbase + 16384u + (uint32_t)(wn * (8 * NI) + (lm >> 1) * 8 + lr) * 128;
        const int bd = lm & 1;
#pragma unroll
        for (int ks = 0; ks < 4; ks++) {
            uint32_t a[4][4], b[NI][2];
#pragma unroll
            for (int mi = 0; mi < 4; mi++) {
                uint32_t addr = a_base + (uint32_t)(mi * 16 * 128) + ((uint32_t)((2 * ks + ad) ^ lr) << 4);
                LDMATRIX_X4(a[mi][0], a[mi][1], a[mi][2], a[mi][3], addr);
            }
#pragma unroll
            for (int np = 0; np < NI / 2; np++) {
                uint32_t addr = b_base + (uint32_t)(np * 16 * 128) + ((uint32_t)((2 * ks + bd) ^ lr) << 4);
                LDMATRIX_X4(b[2 * np][0], b[2 * np][1], b[2 * np + 1][0], b[2 * np + 1][1], addr);
            }
#pragma unroll
            for (int mi = 0; mi < 4; mi++)
#pragma unroll
                for (int ni = 0; ni < NI; ni++)
                    MMA_F16(acc[mi][ni], a[mi], b[ni]);
        }
    };

    // STAGES-deep pipeline, one __syncthreads per K-tile.
    {
        int pre = (nt < STAGES - 1) ? nt : (STAGES - 1);
        for (int i = 0; i < pre; i++) { load_tile(i, i); CP_COMMIT(); }
    }
    int sc = 0;
    for (int kt = 0; kt < nt; kt++) {
        if (STAGES == 4) {
            if (kt < nt - 2)       { CP_WAIT(2); }
            else if (kt == nt - 2) { CP_WAIT(1); }
            else                   { CP_WAIT(0); }
        } else {
            if (kt < nt - 1)       { CP_WAIT(1); }
            else                   { CP_WAIT(0); }
        }
        __syncthreads();
        compute_tile(sc);
        if (kt + STAGES - 1 < nt) {
            int sl = sc + (STAGES - 1); if (sl >= STAGES) sl -= STAGES;
            load_tile(kt + STAGES - 1, sl);
            CP_COMMIT();
        }
        if (++sc == STAGES) sc = 0;
    }

    if (ACT == 5) {
        // fused LSTM-gate epilogue (interleaved layout) + partial add.
        // Warp covers NI/4 gate blocks of 32 cols (ni quads map to I,F,O,C).
#pragma unroll
        for (int blk = 0; blk < NI / 4; blk++) {
            const int base = bn + wn * (8 * NI) + blk * 32;
            if (base >= Nd) continue;
            const int ub = base >> 5;
            const int u = ub * 8 + 2 * t;
            const int colI = base + 2 * t;
            const float bI0 = bias[colI],      bI1 = bias[colI + 1];
            const float bF0 = bias[colI + 8],  bF1 = bias[colI + 9];
            const float bO0 = bias[colI + 16], bO1 = bias[colI + 17];
            const float bC0 = bias[colI + 24], bC1 = bias[colI + 25];
#pragma unroll
            for (int mi = 0; mi < 4; mi++) {
                const int r0 = bm + wm * 64 + mi * 16 + g;
#pragma unroll
                for (int half_ = 0; half_ < 2; half_++) {
                    const int r = r0 + half_ * 8;
                    const int e0 = half_ * 2, e1 = half_ * 2 + 1;
                    const float* prow = partial + (size_t)r * NG + colI;
                    float2 pI = *(const float2*)(prow);
                    float2 pF = *(const float2*)(prow + 8);
                    float2 pO = *(const float2*)(prow + 16);
                    float2 pC = *(const float2*)(prow + 24);
                    float I0 = sigmoidf_(acc[mi][blk * 4 + 0][e0] + pI.x + bI0);
                    float I1 = sigmoidf_(acc[mi][blk * 4 + 0][e1] + pI.y + bI1);
                    float F0 = sigmoidf_(acc[mi][blk * 4 + 1][e0] + pF.x + bF0);
                    float F1 = sigmoidf_(acc[mi][blk * 4 + 1][e1] + pF.y + bF1);
                    float O0 = sigmoidf_(acc[mi][blk * 4 + 2][e0] + pO.x + bO0);
                    float O1 = sigmoidf_(acc[mi][blk * 4 + 2][e1] + pO.y + bO1);
                    float T0 = tanhf(acc[mi][blk * 4 + 3][e0] + pC.x + bC0);
                    float T1 = tanhf(acc[mi][blk * 4 + 3][e1] + pC.y + bC1);
                    float2 cv = *(const float2*)(cells + (size_t)r * U + u);
                    float c0 = F0 * cv.x + I0 * T0;
                    float c1 = F1 * cv.y + I1 * T1;
                    float hh0 = O0 * tanhf(c0);
                    float hh1 = O1 * tanhf(c1);
                    *(float2*)(outC + (size_t)r * U + u) = make_float2(c0, c1);
                    *(float2*)(outH + (size_t)r * U + u) = make_float2(hh0, hh1);
                    *(__half2*)(outHh + (size_t)r * U + u) = __floats2half2_rn(hh0, hh1);
                }
            }
        }
        return;
    }

#pragma unroll
    for (int ni = 0; ni < NI; ni++) {
        const int col0 = bn + wn * (8 * NI) + ni * 8 + 2 * t;
        if (col0 >= Nd) continue;
        const float b0 = bias ? bias[col0] : 0.f;
        const float b1 = bias ? bias[col0 + 1] : 0.f;
#pragma unroll
        for (int mi = 0; mi < 4; mi++) {
            const int r0 = bm + wm * 64 + mi * 16 + g;
            float v0 = act_apply(acc[mi][ni][0] + b0, ACT);
            float v1 = act_apply(acc[mi][ni][1] + b1, ACT);
            float v2 = act_apply(acc[mi][ni][2] + b0, ACT);
            float v3 = act_apply(acc[mi][ni][3] + b1, ACT);
            if (HOUT) {
                __half* C = (__half*)Cv;
                *(__half2*)(C + (size_t)r0 * ldc + col0)       = __floats2half2_rn(v0, v1);
                *(__half2*)(C + (size_t)(r0 + 8) * ldc + col0) = __floats2half2_rn(v2, v3);
            } else {
                float* C = (float*)Cv;
                *(float2*)(C + (size_t)r0 * ldc + col0)       = make_float2(v0, v1);
                *(float2*)(C + (size_t)(r0 + 8) * ldc + col0) = make_float2(v2, v3);
            }
        }
    }
}

// ================= fast weight transpose + fp16 =================
// W (K,N) f32 -> Wt (N,K) f16. 64x64 tiles, float4 loads, 16B stores.
// PERM: output row = (n>>3)*32 + gate*8 + (n&7)
template <bool PERM>
__global__ void wtrans_k(const float* __restrict__ W, __half* __restrict__ Wt,
                         int K, int N, int gate) {
    __shared__ float ts[64][65];
    const int kb = blockIdx.y * 64, nb = blockIdx.x * 64;
    const int tid = threadIdx.x;
#pragma unroll
    for (int i = 0; i < 4; i++) {
        int idx = tid + i * 256;
        int k = idx >> 4, q = idx & 15;
        int gk = kb + k, gn = nb + q * 4;
        float4 v = make_float4(0.f, 0.f, 0.f, 0.f);
        if (gk < K && gn < N) v = *(const float4*)(W + (size_t)gk * N + gn);
        ts[k][q * 4 + 0] = v.x;
        ts[k][q * 4 + 1] = v.y;
        ts[k][q * 4 + 2] = v.z;
        ts[k][q * 4 + 3] = v.w;
    }
    __syncthreads();
#pragma unroll
    for (int i = 0; i < 2; i++) {
        int idx = tid + i * 256;
        int n = idx >> 3, c = idx & 7;
        int gn = nb + n;
        int gk = kb + c * 8;
        if (gn >= N || gk >= K) continue;
        __half hv[8];
#pragma unroll
        for (int j = 0; j < 8; j++) hv[j] = __float2half_rn(ts[c * 8 + j][n]);
        int row = PERM ? (((gn >> 3) << 5) + gate * 8 + (gn & 7)) : gn;
        *(uint4*)(Wt + (size_t)row * K + gk) = *(uint4*)hv;
    }
}

// ================= pointwise kernels =================
__global__ void transpose_z_k(const float* __restrict__ z, __half* __restrict__ zb) {
    int idx = blockIdx.x * blockDim.x + threadIdx.x;
    if (idx >= ROWS * DT) return;
    int bn = idx / DT;
    int rem = idx - bn * DT;
    int d = rem / Tt;
    int t = rem - d * Tt;
    int b = bn >> 3;
    int n = bn & 7;
    zb[idx] = __float2half_rn(z[((size_t)(b * Tt + t) * Ns + n) * Dd + d]);
}

__global__ void round_copy_k(const float* __restrict__ src, __half* __restrict__ dst, int n) {
    int idx = blockIdx.x * blockDim.x + threadIdx.x;
    if (idx >= n) return;
    dst[idx] = __float2half_rn(src[idx]);
}

__global__ void fuse_bias_perm_k(const float* __restrict__ bI, const float* __restrict__ bF,
                                 const float* __restrict__ bO, const float* __restrict__ bC,
                                 float* __restrict__ dst) {
    int idx = blockIdx.x * blockDim.x + threadIdx.x;
    if (idx >= NG) return;
    int gate = idx / U, u = idx - gate * U;
    const float* src = (gate == 0) ? bI : (gate == 1) ? bF : (gate == 2) ? bO : bC;
    dst[((u >> 3) << 5) + gate * 8 + (u & 7)] = src[u];
}

__global__ void pair_combine_k(const __half* __restrict__ ai, int ldi,
                               const __half* __restrict__ aj, int ldj,
                               const float* __restrict__ bias, __half* __restrict__ out) {
    int idx = blockIdx.x * blockDim.x + threadIdx.x;   // over PROWS * (H/2)
    if (idx >= PROWS * (H / 2)) return;
    int row = idx / (H / 2);
    int h2 = idx - row * (H / 2);
    int j = row & 7;
    int i_row = row >> 3;
    int b = i_row >> 3;
    int j_row = (b << 3) + j;

    float2 a = __half22float2(*((const __half2*)(ai + (size_t)i_row * ldi) + h2));
    float2 c = __half22float2(*((const __half2*)(aj + (size_t)j_row * ldj) + h2));
    float2 bb = ((const float2*)bias)[h2];
    float o0 = act_apply(a.x + c.x + bb.x, 2);
    float o1 = act_apply(a.y + c.y + bb.y, 2);
    ((__half2*)(out + (size_t)row * H))[h2] = __floats2half2_rn(o0, o1);
}

__global__ void reduce_inter_k(const __half* __restrict__ rA, const __half* __restrict__ rB,
                               __half* __restrict__ xh) {
    int idx = blockIdx.x * blockDim.x + threadIdx.x;   // over ROWS * (H/2)
    if (idx >= ROWS * (H / 2)) return;
    int row = idx / (H / 2);
    int h2 = idx - row * (H / 2);
    float s0 = 0.f, s1 = 0.f, m0 = -INFINITY, m1 = -INFINITY;
#pragma unroll
    for (int j = 0; j < Ns; j++) {
        size_t p = (size_t)(row * Ns + j) * (H / 2) + h2;
        float2 va = __half22float2(((const __half2*)rA)[p]);
        float2 vb = __half22float2(((const __half2*)rB)[p]);
        float v0 = va.x + vb.x, v1 = va.y + vb.y;
        s0 += v0; s1 += v1;
        m0 = fmaxf(m0, v0); m1 = fmaxf(m1, v1);
    }
    __half* base = xh + (size_t)row * GIN;
    *(__half2*)(base + BUF + 2 * h2)     = __floats2half2_rn(s0, s1);
    *(__half2*)(base + BUF + H + 2 * h2) = __floats2half2_rn(m0, m1);
}

__global__ void copy_hidden_k(const float* __restrict__ hidden, __half* __restrict__ xh) {
    int idx = blockIdx.x * blockDim.x + threadIdx.x;   // over ROWS * (U/2)
    if (idx >= ROWS * (U / 2)) return;
    int row = idx / (U / 2);
    int c2 = idx - row * (U / 2);
    float2 v = ((const float2*)(hidden + (size_t)row * U))[c2];
    *(__half2*)(xh + (size_t)row * GIN + XDIM + 2 * c2) = __floats2half2_rn(v.x, v.y);
}

__global__ void decode_sum_k(const float* __restrict__ p, const float* __restrict__ bias,
                             float* __restrict__ out) {
    int idx = blockIdx.x * blockDim.x + threadIdx.x;   // over DSZ
    if (idx >= DSZ) return;
    int col = idx & (Dd - 1);
    out[idx] = ((p[idx] + p[DSZ + idx]) + (p[2 * DSZ + idx] + p[3 * DSZ + idx])) + bias[col];
}

// ================= host =================
template <int ACT, bool HOUT, int NI>
static void launch_hg(cudaStream_t st,
                      const __half* A, int lda, const __half* Wt, int ldw,
                      const float* bias,
                      void* C, int ldc, int M, int Nd, int K,
                      const float* partial = nullptr,
                      const float* cells = nullptr, float* outC = nullptr,
                      float* outH = nullptr, __half* outHh = nullptr) {
    constexpr int BN = 32 * NI;
    constexpr int STAGES = (NI == 8) ? 4 : 3;
    constexpr int smem = STAGES * ((128 + BN) * 64 * 2);
    cudaFuncSetAttribute(hgemm<ACT, HOUT, NI>, cudaFuncAttributeMaxDynamicSharedMemorySize, smem);
    dim3 grid((Nd + BN - 1) / BN, M / 128);
    hgemm<ACT, HOUT, NI><<<grid, 256, smem, st>>>(A, lda, Wt, ldw, bias, C, ldc, M, Nd, K,
                                                  partial, cells, outC, outH, outHh);
}

template <bool PERM>
static void launch_wtrans(cudaStream_t st, const float* W, __half* Wt, int K, int N, int gate = 0) {
    dim3 grid((N + 63) / 64, (K + 63) / 64);
    wtrans_k<PERM><<<grid, 256, 0, st>>>(W, Wt, K, N, gate);
}

// Persistent stream/event pool (created once on the pre-baseline correctness
// run; reused by every captured call; never destroyed).
namespace {
struct StreamPool {
    cudaStream_t s1, s2, s3;
    cudaEvent_t evFork, evS1, evProj, evBl, evS2, evGate, evD1, evD2, evD3;
    StreamPool() {
        cudaStreamCreateWithFlags(&s1, cudaStreamNonBlocking);
        cudaStreamCreateWithFlags(&s2, cudaStreamNonBlocking);
        cudaStreamCreateWithFlags(&s3, cudaStreamNonBlocking);
        cudaEventCreateWithFlags(&evFork, cudaEventDisableTiming);
        cudaEventCreateWithFlags(&evS1,   cudaEventDisableTiming);
        cudaEventCreateWithFlags(&evProj, cudaEventDisableTiming);
        cudaEventCreateWithFlags(&evBl,   cudaEventDisableTiming);
        cudaEventCreateWithFlags(&evS2,   cudaEventDisableTiming);
        cudaEventCreateWithFlags(&evGate, cudaEventDisableTiming);
        cudaEventCreateWithFlags(&evD1,   cudaEventDisableTiming);
        cudaEventCreateWithFlags(&evD2,   cudaEventDisableTiming);
        cudaEventCreateWithFlags(&evD3,   cudaEventDisableTiming);
    }
};
}

extern "C" void kernel_launch(void* const* d_in, const int* in_sizes, int n_in,
                              void* d_out, int out_size) {
    const float* z      = (const float*)d_in[0];
    const float* Cells  = (const float*)d_in[1];
    const float* hidden = (const float*)d_in[2];
    const float* W_buf  = (const float*)d_in[3];
    const float* b_buf  = (const float*)d_in[4];
    const float* W_r1   = (const float*)d_in[5];
    const float* b_r1   = (const float*)d_in[6];
    const float* W_r2   = (const float*)d_in[7];
    const float* b_r2   = (const float*)d_in[8];
    const float* W_r3   = (const float*)d_in[9];
    const float* b_r3   = (const float*)d_in[10];
    const float* W_l1   = (const float*)d_in[11];
    const float* b_l1   = (const float*)d_in[12];
    const float* W_l2   = (const float*)d_in[13];
    const float* b_l2   = (const float*)d_in[14];
    const float* W_l3   = (const float*)d_in[15];
    const float* b_l3   = (const float*)d_in[16];
    const float* W_I    = (const float*)d_in[17];
    const float* b_I    = (const float*)d_in[18];
    const float* W_F    = (const float*)d_in[19];
    const float* b_F    = (const float*)d_in[20];
    const float* W_O    = (const float*)d_in[21];
    const float* b_O    = (const float*)d_in[22];
    const float* W_C    = (const float*)d_in[23];
    const float* b_C    = (const float*)d_in[24];
    const float* W_d    = (const float*)d_in[25];
    const float* b_d    = (const float*)d_in[26];

    float* out = (float*)d_out;

    __half *wt, *zb, *cellsH, *proj, *bl, *rA, *rB, *rC, *rD, *xh, *hnewH;
    float *biasG, *gpart, *gdec;
    cudaGetSymbolAddress((void**)&wt, h_wt);
    cudaGetSymbolAddress((void**)&zb, h_zb);
    cudaGetSymbolAddress((void**)&cellsH, h_cells);
    cudaGetSymbolAddress((void**)&proj, h_proj);
    cudaGetSymbolAddress((void**)&bl, h_bl);
    cudaGetSymbolAddress((void**)&rA, h_rA);
    cudaGetSymbolAddress((void**)&rB, h_rB);
    cudaGetSymbolAddress((void**)&rC, h_rC);
    cudaGetSymbolAddress((void**)&rD, h_rD);
    cudaGetSymbolAddress((void**)&xh, h_xh);
    cudaGetSymbolAddress((void**)&hnewH, h_hnew);
    cudaGetSymbolAddress((void**)&biasG, g_bias);
    cudaGetSymbolAddress((void**)&gpart, g_part);
    cudaGetSymbolAddress((void**)&gdec, g_dec);

    static StreamPool pool;
    cudaStream_t s1 = pool.s1, s2 = pool.s2, s3 = pool.s3;
    cudaStream_t m = 0;       // capturing (legacy) stream

    cudaEventRecord(pool.evFork, m);

    // ---- s1: gate weights (full-K transposes) + hidden-slice partial gate GEMM
    cudaStreamWaitEvent(s1, pool.evFork, 0);
    launch_wtrans<true>(s1, W_I, wt + OFF_G, GIN, U, 0);
    launch_wtrans<true>(s1, W_F, wt + OFF_G, GIN, U, 1);
    launch_wtrans<true>(s1, W_O, wt + OFF_G, GIN, U, 2);
    launch_wtrans<true>(s1, W_C, wt + OFF_G, GIN, U, 3);
    fuse_bias_perm_k<<<(NG + 255) / 256, 256, 0, s1>>>(b_I, b_F, b_O, b_C, biasG);
    copy_hidden_k<<<(ROWS * (U / 2) + 255) / 256, 256, 0, s1>>>(hidden, xh);
    // pass 1: gpart = xh[:, XDIM:] @ Wg[:, XDIM:]^T  (K = U), NI=4, 2 CTA/SM
    launch_hg<0, false, 4>(s1, xh + XDIM, GIN, wt + OFF_G + XDIM, GIN, nullptr,
                           gpart, NG, ROWS, NG, U);
    cudaEventRecord(pool.evS1, s1);

    // ---- s2: projection path (concurrent with main's buffer GEMM)
    cudaStreamWaitEvent(s2, pool.evFork, 0);
    launch_wtrans<false>(s2, W_r1,                 wt + OFF_R1A, U, H);
    launch_wtrans<false>(s2, W_r1 + (size_t)U * H, wt + OFF_R1B, U, H);
    launch_wtrans<false>(s2, W_l1,                 wt + OFF_L1A, U, H);
    round_copy_k<<<(ROWS * U + 255) / 256, 256, 0, s2>>>(Cells, cellsH, ROWS * U);
    launch_hg<0, true, 4>(s2, cellsH, U, wt + OFF_R1A, U, nullptr, proj, 1536, ROWS, 1536, U);
    cudaEventRecord(pool.evProj, s2);
    launch_wtrans<false>(s2, W_l2, wt + OFF_L2, H, H);
    launch_wtrans<false>(s2, W_l3, wt + OFF_L3, H, H);

    // ---- main: buffer path FIRST (critical for evBl), deferred small wtrans after
    transpose_z_k<<<(ROWS * DT + 255) / 256, 256, 0, m>>>(z, zb);
    launch_wtrans<false>(m, W_buf, wt + OFF_BUF, DT, BUF);
    launch_wtrans<false>(m, W_l1 + (size_t)U * H, wt + OFF_L1B, BUF, H);
    launch_hg<1, true, 4>(m, zb, DT, wt + OFF_BUF, DT, b_buf, xh, GIN, ROWS, BUF, DT);
    launch_hg<0, true, 4>(m, xh, GIN, wt + OFF_L1B, BUF, nullptr, bl, H, ROWS, H, BUF);
    cudaEventRecord(pool.evBl, m);
    launch_wtrans<false>(m, W_r2, wt + OFF_R2, H, H);
    launch_wtrans<false>(m, W_r3, wt + OFF_R3, H, H);
    launch_wtrans<false>(m, W_d, wt + OFF_D, U, Dd);

    // ---- s2: lambda path (combine -> rC, l2 -> rD, l3 -> rC), 2-CTA/SM NI=4 GEMMs
    cudaStreamWaitEvent(s2, pool.evBl, 0);
    pair_combine_k<<<(PROWS * (H / 2) + 255) / 256, 256, 0, s2>>>(proj + 1024, 1536, bl, H, b_l1, rC);
    launch_hg<2, true, 4>(s2, rC, H, wt + OFF_L2, H, b_l2, rD, H, PROWS, H, H);
    launch_hg<2, true, 4>(s2, rD, H, wt + OFF_L3, H, b_l3, rC, H, PROWS, H, H);
    cudaEventRecord(pool.evS2, s2);

    // ---- main: rho path (combine -> rA, r2 -> rB, r3 -> rA)
    cudaStreamWaitEvent(m, pool.evProj, 0);
    pair_combine_k<<<(PROWS * (H / 2) + 255) / 256, 256, 0, m>>>(proj, 1536, proj + 512, 1536, b_r1, rA);
    launch_hg<2, true, 4>(m, rA, H, wt + OFF_R2, H, b_r2, rB, H, PROWS, H, H);
    launch_hg<2, true, 4>(m, rB, H, wt + OFF_R3, H, b_r3, rA, H, PROWS, H, H);

    // ---- join: reduce, then final gate pass (K = XDIM, NI=4, 2 CTA/SM) + LSTM epilogue
    cudaStreamWaitEvent(m, pool.evS2, 0);
    reduce_inter_k<<<(ROWS * (H / 2) + 255) / 256, 256, 0, m>>>(rA, rC, xh);
    cudaStreamWaitEvent(m, pool.evS1, 0);
    launch_hg<5, false, 4>(m, xh, GIN, wt + OFF_G, GIN, biasG,
                           nullptr, 0, ROWS, NG, XDIM,
                           gpart, Cells, out + OUT_OFF_C, out + OUT_OFF_H, hnewH);
    cudaEventRecord(pool.evGate, m);

    // ---- decode: split-K x4 on 4 streams (NI=2 -> BN=64, exact fit)
    launch_hg<0, false, 2>(m, hnewH, U, wt + OFF_D, U, nullptr,
                           gdec + 0 * DSZ, Dd, ROWS, Dd, 512);
    cudaStreamWaitEvent(s1, pool.evGate, 0);
    launch_hg<0, false, 2>(s1, hnewH + 512, U, wt + OFF_D + 512, U, nullptr,
                           gdec + 1 * DSZ, Dd, ROWS, Dd, 512);
    cudaEventRecord(pool.evD1, s1);
    cudaStreamWaitEvent(s2, pool.evGate, 0);
    launch_hg<0, false, 2>(s2, hnewH + 1024, U, wt + OFF_D + 1024, U, nullptr,
                           gdec + 2 * DSZ, Dd, ROWS, Dd, 512);
    cudaEventRecord(pool.evD2, s2);
    cudaStreamWaitEvent(s3, pool.evGate, 0);
    launch_hg<0, false, 2>(s3, hnewH + 1536, U, wt + OFF_D + 1536, U, nullptr,
                           gdec + 3 * DSZ, Dd, ROWS, Dd, 520);
    cudaEventRecord(pool.evD3, s3);

    cudaStreamWaitEvent(m, pool.evD1, 0);
    cudaStreamWaitEvent(m, pool.evD2, 0);
    cudaStreamWaitEvent(m, pool.evD3, 0);
    decode_sum_k<<<(DSZ + 255) / 256, 256, 0, m>>>(gdec, b_d, out);
}